// round 12
// baseline (speedup 1.0000x reference)
#include <cuda_runtime.h>
#include <cuda_bf16.h>
#include <cuda_fp16.h>
#include <cstdint>

#define D_MODEL 1024
#define NHEADS  16
#define HDIM    64
#define WINDOW  256
#define BATCH   2
#define SEQ     2048
#define MTOT    (BATCH * SEQ)          /* 4096 */
#define QKV_LD  (3 * D_MODEL)          /* 3072 */
#define BHTOT   (BATCH * NHEADS)       /* 32 */

// ---- scratch --------------------------------------------------------------
__device__ __half g_xhi[(size_t)MTOT * D_MODEL];
__device__ __half g_xlo[(size_t)MTOT * D_MODEL];
__device__ __half g_wq[(size_t)QKV_LD * D_MODEL];
__device__ __half g_wph[(size_t)D_MODEL * D_MODEL];
// per-head Q/K: [bh][token][e]; V transposed: [bh][e][token]  (fp16 hi/lo)
__device__ __half g_qh[(size_t)BHTOT * SEQ * HDIM];
__device__ __half g_ql[(size_t)BHTOT * SEQ * HDIM];
__device__ __half g_kh[(size_t)BHTOT * SEQ * HDIM];
__device__ __half g_kl[(size_t)BHTOT * SEQ * HDIM];
__device__ __half g_vth[(size_t)BHTOT * HDIM * SEQ];
__device__ __half g_vtl[(size_t)BHTOT * HDIM * SEQ];
__device__ __half g_ahi[(size_t)MTOT * D_MODEL];
__device__ __half g_alo[(size_t)MTOT * D_MODEL];

// ---- PTX helpers ------------------------------------------------------------
__device__ __forceinline__ uint32_t smem_u32(const void* p) {
    uint32_t a;
    asm("{ .reg .u64 t; cvta.to.shared.u64 t, %1; cvt.u32.u64 %0, t; }" : "=r"(a) : "l"(p));
    return a;
}
__device__ __forceinline__ void cp16(uint32_t dst, const void* src) {
    asm volatile("cp.async.cg.shared.global [%0], [%1], 16;" :: "r"(dst), "l"(src));
}
#define CP_COMMIT()  asm volatile("cp.async.commit_group;" ::: "memory")
#define CP_WAIT(n)   asm volatile("cp.async.wait_group %0;" :: "n"(n) : "memory")

__device__ __forceinline__ void mma_f16(float* d, uint32_t a0, uint32_t a1,
                                        uint32_t a2, uint32_t a3,
                                        uint32_t b0, uint32_t b1) {
    asm("mma.sync.aligned.m16n8k16.row.col.f32.f16.f16.f32 "
        "{%0,%1,%2,%3}, {%4,%5,%6,%7}, {%8,%9}, {%0,%1,%2,%3};"
        : "+f"(d[0]), "+f"(d[1]), "+f"(d[2]), "+f"(d[3])
        : "r"(a0), "r"(a1), "r"(a2), "r"(a3), "r"(b0), "r"(b1));
}
// fp16-accumulate variant (2x rate). d0 = halves (r,c),(r,c+1); d1 = (r+8,c),(r+8,c+1)
__device__ __forceinline__ void mma_f16acc(uint32_t* d, uint32_t a0, uint32_t a1,
                                           uint32_t a2, uint32_t a3,
                                           uint32_t b0, uint32_t b1) {
    asm("mma.sync.aligned.m16n8k16.row.col.f16.f16.f16.f16 "
        "{%0,%1}, {%2,%3,%4,%5}, {%6,%7}, {%0,%1};"
        : "+r"(d[0]), "+r"(d[1])
        : "r"(a0), "r"(a1), "r"(a2), "r"(a3), "r"(b0), "r"(b1));
}
__device__ __forceinline__ void fold_lo(float* acc, const uint32_t* lo) {
    float2 f01 = __half22float2(*(const __half2*)&lo[0]);
    float2 f23 = __half22float2(*(const __half2*)&lo[1]);
    acc[0] += f01.x; acc[1] += f01.y; acc[2] += f23.x; acc[3] += f23.y;
}

// ---- splits ------------------------------------------------------------------
__global__ __launch_bounds__(256)
void split_f16(const float4* __restrict__ in, __half* __restrict__ hi,
               __half* __restrict__ lo, int n4)
{
    int i = blockIdx.x * 256 + threadIdx.x;
    if (i >= n4) return;
    float4 v = in[i];
    __half h0 = __float2half(v.x), h1 = __float2half(v.y);
    __half h2 = __float2half(v.z), h3 = __float2half(v.w);
    __half2* hp = (__half2*)(hi + i * 4);
    __half2* lp = (__half2*)(lo + i * 4);
    hp[0] = __half2(h0, h1);
    hp[1] = __half2(h2, h3);
    lp[0] = __half2(__float2half(v.x - __half2float(h0)),
                    __float2half(v.y - __half2float(h1)));
    lp[1] = __half2(__float2half(v.z - __half2float(h2)),
                    __float2half(v.w - __half2float(h3)));
}
__global__ __launch_bounds__(256)
void cvt_half(const float4* __restrict__ in, __half* __restrict__ out, int n4)
{
    int i = blockIdx.x * 256 + threadIdx.x;
    if (i >= n4) return;
    float4 v = in[i];
    __half2* op = (__half2*)(out + i * 4);
    op[0] = __half2(__float2half(v.x), __float2half(v.y));
    op[1] = __half2(__float2half(v.z), __float2half(v.w));
}

// ---- QKV GEMM: fp16 2-term (lo term in fp16 acc); per-head epilogue ----------
#define BM 128
#define BN 128
#define BK 32
#define SROW 40
#define TILE_E (128 * SROW)
#define QSTAGE_E (3 * TILE_E)
#define QSMEM_SZ 66048

__global__ __launch_bounds__(256, 1)
void gemm_qkv(const __half* __restrict__ Ahi, const __half* __restrict__ Alo,
              const __half* __restrict__ W,
              const float* __restrict__ bias,
              __half* __restrict__ qh_o, __half* __restrict__ ql_o,
              __half* __restrict__ kh_o, __half* __restrict__ kl_o,
              __half* __restrict__ vth_o, __half* __restrict__ vtl_o)
{
    extern __shared__ __half smemh[];
    const int K = D_MODEL;
    const int tid  = threadIdx.x;
    const int lane = tid & 31;
    const int wid  = tid >> 5;
    const int wm   = wid >> 2;
    const int wn   = wid & 3;
    const int tr   = lane >> 2;
    const int tc2  = (lane & 3) * 2;
    const int bm   = blockIdx.y * BM;
    const int bn   = blockIdx.x * BN;

    const uint32_t sbase = smem_u32(smemh);

    float acc[4][4][4];
    uint32_t lacc[4][4][2];
#pragma unroll
    for (int i = 0; i < 4; ++i)
#pragma unroll
        for (int j = 0; j < 4; ++j) {
#pragma unroll
            for (int r = 0; r < 4; ++r) acc[i][j][r] = 0.f;
            lacc[i][j][0] = 0u; lacc[i][j][1] = 0u;
        }

    const __half* srcs[3] = { Ahi, Alo, W };
    const int rowoff[3] = { bm, bm, bn };

    auto load_stage = [&](int s, int k0) {
        const uint32_t st = sbase + (uint32_t)(s * QSTAGE_E * 2);
#pragma unroll
        for (int t = 0; t < 3; ++t) {
#pragma unroll
            for (int g2 = 0; g2 < 2; ++g2) {
                const int g = tid + g2 * 256;
                const int row = g >> 2, part = g & 3;
                const uint32_t dst = st + (uint32_t)(t * TILE_E + row * SROW + part * 8) * 2;
                const __half* src = srcs[t] + (size_t)(rowoff[t] + row) * K + k0 + part * 8;
                cp16(dst, src);
            }
        }
    };

    const int KCH = K / BK;
    load_stage(0, 0);
    CP_COMMIT();

    for (int c = 0; c < KCH; ++c) {
        if (c + 1 < KCH) { load_stage((c + 1) & 1, (c + 1) * BK); CP_COMMIT(); CP_WAIT(1); }
        else             { CP_WAIT(0); }
        __syncthreads();

        const __half* stg = smemh + (c & 1) * QSTAGE_E;
        const __half* Ah = stg;
        const __half* Al = stg + TILE_E;
        const __half* Bh = stg + 2 * TILE_E;

#pragma unroll
        for (int k0 = 0; k0 < BK; k0 += 16) {
            uint32_t ah[4][4], al[4][4], bh[4][2];
#pragma unroll
            for (int mi = 0; mi < 4; ++mi) {
                const int base = (wm * 64 + mi * 16 + tr) * SROW + k0 + tc2;
                ah[mi][0] = *(const uint32_t*)(Ah + base);
                ah[mi][1] = *(const uint32_t*)(Ah + base + 8 * SROW);
                ah[mi][2] = *(const uint32_t*)(Ah + base + 8);
                ah[mi][3] = *(const uint32_t*)(Ah + base + 8 * SROW + 8);
                al[mi][0] = *(const uint32_t*)(Al + base);
                al[mi][1] = *(const uint32_t*)(Al + base + 8 * SROW);
                al[mi][2] = *(const uint32_t*)(Al + base + 8);
                al[mi][3] = *(const uint32_t*)(Al + base + 8 * SROW + 8);
            }
#pragma unroll
            for (int ni = 0; ni < 4; ++ni) {
                const int base = (wn * 32 + ni * 8 + tr) * SROW + k0 + tc2;
                bh[ni][0] = *(const uint32_t*)(Bh + base);
                bh[ni][1] = *(const uint32_t*)(Bh + base + 8);
            }
#pragma unroll
            for (int mi = 0; mi < 4; ++mi)
#pragma unroll
                for (int ni = 0; ni < 4; ++ni)
                    mma_f16(acc[mi][ni], ah[mi][0], ah[mi][1], ah[mi][2], ah[mi][3],
                            bh[ni][0], bh[ni][1]);
#pragma unroll
            for (int mi = 0; mi < 4; ++mi)
#pragma unroll
                for (int ni = 0; ni < 4; ++ni)
                    mma_f16acc(lacc[mi][ni], al[mi][0], al[mi][1], al[mi][2], al[mi][3],
                               bh[ni][0], bh[ni][1]);
        }
        __syncthreads();
    }

    // fold fp16 lo accumulators
#pragma unroll
    for (int mi = 0; mi < 4; ++mi)
#pragma unroll
        for (int ni = 0; ni < 4; ++ni)
            fold_lo(acc[mi][ni], lacc[mi][ni]);

    // ---- epilogue: fp16 hi/lo Q/K + transposed V ----
    if (bn < 2 * D_MODEL) {
        __half* H = (bn < D_MODEL) ? qh_o : kh_o;
        __half* L = (bn < D_MODEL) ? ql_o : kl_o;
        const int roff = (bn < D_MODEL) ? bn : bn - D_MODEL;
#pragma unroll
        for (int mi = 0; mi < 4; ++mi) {
            const int r = bm + wm * 64 + mi * 16 + tr;
            const int b = r >> 11, row = r & 2047;
#pragma unroll
            for (int ni = 0; ni < 4; ++ni) {
                const int cl = wn * 32 + ni * 8 + tc2;
                const float b0 = bias[bn + cl], b1 = bias[bn + cl + 1];
                const int cg = roff + cl, hh = cg >> 6, e = cg & 63;
                const size_t base =
                    (((size_t)b * NHEADS + hh) * SEQ + row) * HDIM + e;
                float v0 = acc[mi][ni][0] + b0, v1 = acc[mi][ni][1] + b1;
                float v2 = acc[mi][ni][2] + b0, v3 = acc[mi][ni][3] + b1;
                __half h0 = __float2half(v0), h1 = __float2half(v1);
                __half h2 = __float2half(v2), h3 = __float2half(v3);
                __half2 u01(h0, h1), u23(h2, h3);
                __half2 l01(__float2half(v0 - __half2float(h0)),
                            __float2half(v1 - __half2float(h1)));
                __half2 l23(__float2half(v2 - __half2float(h2)),
                            __float2half(v3 - __half2float(h3)));
                *(__half2*)(H + base) = u01;
                *(__half2*)(L + base) = l01;
                *(__half2*)(H + base + 8 * HDIM) = u23;
                *(__half2*)(L + base + 8 * HDIM) = l23;
            }
        }
    } else {
        float* sf = (float*)smemh;
#pragma unroll
        for (int mi = 0; mi < 4; ++mi) {
            const int r0 = wm * 64 + mi * 16 + tr;
#pragma unroll
            for (int ni = 0; ni < 4; ++ni) {
                const int cl = wn * 32 + ni * 8 + tc2;
                const float b0 = bias[bn + cl], b1 = bias[bn + cl + 1];
                sf[r0 * 129 + cl]           = acc[mi][ni][0] + b0;
                sf[r0 * 129 + cl + 1]       = acc[mi][ni][1] + b1;
                sf[(r0 + 8) * 129 + cl]     = acc[mi][ni][2] + b0;
                sf[(r0 + 8) * 129 + cl + 1] = acc[mi][ni][3] + b1;
            }
        }
        __syncthreads();
        for (int idx = tid; idx < 128 * 64; idx += 256) {
            const int el = idx >> 6, rp = idx & 63;
            const float f0 = sf[(2 * rp) * 129 + el];
            const float f1 = sf[(2 * rp + 1) * 129 + el];
            const int cg = bn - 2 * D_MODEL + el, hh = cg >> 6, e = cg & 63;
            const int rg = bm + 2 * rp, b = rg >> 11, row = rg & 2047;
            const size_t base = (((size_t)b * NHEADS + hh) * HDIM + e) * SEQ + row;
            __half h0 = __float2half(f0), h1 = __float2half(f1);
            __half2 u(h0, h1);
            __half2 l(__float2half(f0 - __half2float(h0)),
                      __float2half(f1 - __half2float(h1)));
            *(__half2*)(vth_o + base) = u;
            *(__half2*)(vtl_o + base) = l;
        }
    }
}

// ---- swa: fp16 2-term, lo passes in fp16 acc ---------------------------------
#define SROW2 72
#define QT (64 * SROW2)
#define SWA_SMEM (10 * QT * 2)

__global__ __launch_bounds__(128, 2)
void swa_tensor(const __half* __restrict__ qh_g, const __half* __restrict__ ql_g,
                const __half* __restrict__ kh_g, const __half* __restrict__ kl_g,
                const __half* __restrict__ vth_g, const __half* __restrict__ vtl_g,
                __half* __restrict__ ahi, __half* __restrict__ alo)
{
    extern __shared__ __half smf[];
    const int tid = threadIdx.x, lane = tid & 31, w = tid >> 5;
    const int bh = blockIdx.y;
    const int q0 = blockIdx.x * 64;
    const int tr = lane >> 2, tc2 = (lane & 3) * 2;

    const uint32_t sQh = smem_u32(smf);

    const size_t qkbase = (size_t)bh * SEQ * HDIM;
    const size_t vbase  = (size_t)bh * HDIM * SEQ;

    auto load_qk = [&](uint32_t sdst, const __half* src) {
#pragma unroll
        for (int it = 0; it < 4; ++it) {
            const int g = it * 128 + tid;
            const int row = g >> 3, ch = g & 7;
            cp16(sdst + (uint32_t)(row * SROW2 + ch * 8) * 2,
                 src + (size_t)row * HDIM + ch * 8);
        }
    };
    auto load_vt = [&](uint32_t sdst, const __half* src) {
#pragma unroll
        for (int it = 0; it < 4; ++it) {
            const int g = it * 128 + tid;
            const int row = g >> 3, ch = g & 7;
            cp16(sdst + (uint32_t)(row * SROW2 + ch * 8) * 2,
                 src + (size_t)row * SEQ + ch * 8);
        }
    };
    auto issue_stage = [&](int s, int j0) {
        const uint32_t st = sQh + (uint32_t)((2 + 4 * s) * QT) * 2;
        load_qk(st,              kh_g + qkbase + (size_t)j0 * HDIM);
        load_qk(st + QT * 2,     kl_g + qkbase + (size_t)j0 * HDIM);
        load_vt(st + 2 * QT * 2, vth_g + vbase + j0);
        load_vt(st + 3 * QT * 2, vtl_g + vbase + j0);
    };

    const int kt0 = max(0, (int)blockIdx.x - 4);
    const int kt1 = blockIdx.x;

    load_qk(sQh, qh_g + qkbase + (size_t)q0 * HDIM);
    load_qk(sQh + QT * 2, ql_g + qkbase + (size_t)q0 * HDIM);
    issue_stage(0, kt0 * 64);
    CP_COMMIT();

    uint32_t qh[4][4], ql[4][4];
    float o[8][4];
#pragma unroll
    for (int ni = 0; ni < 8; ++ni)
#pragma unroll
        for (int j = 0; j < 4; ++j) o[ni][j] = 0.f;
    float m0 = -1e30f, m1 = -1e30f, l0 = 0.f, l1 = 0.f;
    const int i0 = q0 + w * 16 + tr;
    const int i1 = i0 + 8;

    for (int kt = kt0; kt <= kt1; ++kt) {
        const int s = (kt - kt0) & 1;
        if (kt + 1 <= kt1) { issue_stage(s ^ 1, (kt + 1) * 64); CP_COMMIT(); CP_WAIT(1); }
        else               { CP_WAIT(0); }
        __syncthreads();

        if (kt == kt0) {
            const __half* Qh = smf;
            const __half* Ql = smf + QT;
#pragma unroll
            for (int ks = 0; ks < 4; ++ks) {
                const int base = (w * 16 + tr) * SROW2 + ks * 16 + tc2;
                qh[ks][0] = *(const uint32_t*)(Qh + base);
                qh[ks][1] = *(const uint32_t*)(Qh + base + 8 * SROW2);
                qh[ks][2] = *(const uint32_t*)(Qh + base + 8);
                qh[ks][3] = *(const uint32_t*)(Qh + base + 8 * SROW2 + 8);
                ql[ks][0] = *(const uint32_t*)(Ql + base);
                ql[ks][1] = *(const uint32_t*)(Ql + base + 8 * SROW2);
                ql[ks][2] = *(const uint32_t*)(Ql + base + 8);
                ql[ks][3] = *(const uint32_t*)(Ql + base + 8 * SROW2 + 8);
            }
        }

        const __half* Kh  = smf + (2 + 4 * s) * QT;
        const __half* Kl  = Kh + QT;
        const __half* Vth = Kh + 2 * QT;
        const __half* Vtl = Kh + 3 * QT;
        const int j0 = kt * 64;

        // ---- S = Q K^T : main f32-acc + corrections f16-acc ----
        float sacc[8][4];
        uint32_t slo[8][2];
#pragma unroll
        for (int ni = 0; ni < 8; ++ni) {
#pragma unroll
            for (int j = 0; j < 4; ++j) sacc[ni][j] = 0.f;
            slo[ni][0] = 0u; slo[ni][1] = 0u;
        }
#pragma unroll
        for (int ks = 0; ks < 4; ++ks) {
            uint32_t kb[8][2], klr[8][2];
#pragma unroll
            for (int ni = 0; ni < 8; ++ni) {
                const int base = (ni * 8 + tr) * SROW2 + ks * 16 + tc2;
                kb[ni][0]  = *(const uint32_t*)(Kh + base);
                kb[ni][1]  = *(const uint32_t*)(Kh + base + 8);
                klr[ni][0] = *(const uint32_t*)(Kl + base);
                klr[ni][1] = *(const uint32_t*)(Kl + base + 8);
            }
#pragma unroll
            for (int ni = 0; ni < 8; ++ni)
                mma_f16(sacc[ni], qh[ks][0], qh[ks][1], qh[ks][2], qh[ks][3],
                        kb[ni][0], kb[ni][1]);
#pragma unroll
            for (int ni = 0; ni < 8; ++ni)
                mma_f16acc(slo[ni], ql[ks][0], ql[ks][1], ql[ks][2], ql[ks][3],
                           kb[ni][0], kb[ni][1]);
#pragma unroll
            for (int ni = 0; ni < 8; ++ni)
                mma_f16acc(slo[ni], qh[ks][0], qh[ks][1], qh[ks][2], qh[ks][3],
                           klr[ni][0], klr[ni][1]);
        }
#pragma unroll
        for (int ni = 0; ni < 8; ++ni) fold_lo(sacc[ni], slo[ni]);

        // ---- mask + online softmax ----
        float tmax0 = -1e30f, tmax1 = -1e30f;
#pragma unroll
        for (int ni = 0; ni < 8; ++ni) {
            const int ja = j0 + ni * 8 + tc2, jb = ja + 1;
            sacc[ni][0] = (ja <= i0 && (i0 - ja) < WINDOW) ? sacc[ni][0] * 0.125f : -1e30f;
            sacc[ni][1] = (jb <= i0 && (i0 - jb) < WINDOW) ? sacc[ni][1] * 0.125f : -1e30f;
            sacc[ni][2] = (ja <= i1 && (i1 - ja) < WINDOW) ? sacc[ni][2] * 0.125f : -1e30f;
            sacc[ni][3] = (jb <= i1 && (i1 - jb) < WINDOW) ? sacc[ni][3] * 0.125f : -1e30f;
            tmax0 = fmaxf(tmax0, fmaxf(sacc[ni][0], sacc[ni][1]));
            tmax1 = fmaxf(tmax1, fmaxf(sacc[ni][2], sacc[ni][3]));
        }
        tmax0 = fmaxf(tmax0, __shfl_xor_sync(0xffffffff, tmax0, 1));
        tmax0 = fmaxf(tmax0, __shfl_xor_sync(0xffffffff, tmax0, 2));
        tmax1 = fmaxf(tmax1, __shfl_xor_sync(0xffffffff, tmax1, 1));
        tmax1 = fmaxf(tmax1, __shfl_xor_sync(0xffffffff, tmax1, 2));

        const float mn0 = fmaxf(m0, tmax0), mn1 = fmaxf(m1, tmax1);
        const float sc0 = __expf(m0 - mn0), sc1 = __expf(m1 - mn1);
        m0 = mn0; m1 = mn1;

        float rs0 = 0.f, rs1 = 0.f;
        uint32_t ph[8][2], pl[8][2];
#pragma unroll
        for (int ni = 0; ni < 8; ++ni) {
            float p0 = __expf(sacc[ni][0] - mn0);
            float p1 = __expf(sacc[ni][1] - mn0);
            float p2 = __expf(sacc[ni][2] - mn1);
            float p3 = __expf(sacc[ni][3] - mn1);
            rs0 += p0 + p1; rs1 += p2 + p3;
            __half b0 = __float2half(p0), b1 = __float2half(p1);
            __half b2 = __float2half(p2), b3 = __float2half(p3);
            __half2 t01(b0, b1), t23(b2, b3);
            __half2 w01(__float2half(p0 - __half2float(b0)),
                        __float2half(p1 - __half2float(b1)));
            __half2 w23(__float2half(p2 - __half2float(b2)),
                        __float2half(p3 - __half2float(b3)));
            ph[ni][0] = *(uint32_t*)&t01;
            ph[ni][1] = *(uint32_t*)&t23;
            pl[ni][0] = *(uint32_t*)&w01;
            pl[ni][1] = *(uint32_t*)&w23;
        }
        rs0 += __shfl_xor_sync(0xffffffff, rs0, 1);
        rs0 += __shfl_xor_sync(0xffffffff, rs0, 2);
        rs1 += __shfl_xor_sync(0xffffffff, rs1, 1);
        rs1 += __shfl_xor_sync(0xffffffff, rs1, 2);
        l0 = l0 * sc0 + rs0;
        l1 = l1 * sc1 + rs1;

#pragma unroll
        for (int ni = 0; ni < 8; ++ni) {
            o[ni][0] *= sc0; o[ni][1] *= sc0;
            o[ni][2] *= sc1; o[ni][3] *= sc1;
        }

        // ---- O += P V : main f32-acc + corrections f16-acc ----
        uint32_t olo[8][2];
#pragma unroll
        for (int ni = 0; ni < 8; ++ni) { olo[ni][0] = 0u; olo[ni][1] = 0u; }
#pragma unroll
        for (int ks = 0; ks < 4; ++ks) {
            uint32_t vb[8][2], vl[8][2];
#pragma unroll
            for (int ni = 0; ni < 8; ++ni) {
                const int base = (ni * 8 + tr) * SROW2 + ks * 16 + tc2;
                vb[ni][0] = *(const uint32_t*)(Vth + base);
                vb[ni][1] = *(const uint32_t*)(Vth + base + 8);
                vl[ni][0] = *(const uint32_t*)(Vtl + base);
                vl[ni][1] = *(const uint32_t*)(Vtl + base + 8);
            }
#pragma unroll
            for (int ni = 0; ni < 8; ++ni)
                mma_f16(o[ni], ph[2*ks][0], ph[2*ks][1], ph[2*ks+1][0], ph[2*ks+1][1],
                        vb[ni][0], vb[ni][1]);
#pragma unroll
            for (int ni = 0; ni < 8; ++ni)
                mma_f16acc(olo[ni], pl[2*ks][0], pl[2*ks][1], pl[2*ks+1][0], pl[2*ks+1][1],
                           vb[ni][0], vb[ni][1]);
#pragma unroll
            for (int ni = 0; ni < 8; ++ni)
                mma_f16acc(olo[ni], ph[2*ks][0], ph[2*ks][1], ph[2*ks+1][0], ph[2*ks+1][1],
                           vl[ni][0], vl[ni][1]);
        }
#pragma unroll
        for (int ni = 0; ni < 8; ++ni) fold_lo(o[ni], olo[ni]);
        __syncthreads();
    }

    const int b = bh >> 4, h = bh & 15;
    const float inv0 = 1.f / l0, inv1 = 1.f / l1;
    const size_t t0 = (size_t)(b * SEQ + i0) * D_MODEL + (size_t)h * HDIM;
    const size_t t1 = (size_t)(b * SEQ + i1) * D_MODEL + (size_t)h * HDIM;
#pragma unroll
    for (int ni = 0; ni < 8; ++ni) {
        const int c = ni * 8 + tc2;
        float f0 = o[ni][0] * inv0, f1 = o[ni][1] * inv0;
        float f2 = o[ni][2] * inv1, f3 = o[ni][3] * inv1;
        __half h0 = __float2half(f0), h1 = __float2half(f1);
        __half h2 = __float2half(f2), h3 = __float2half(f3);
        __half2 u01(h0, h1), u23(h2, h3);
        __half2 l01(__float2half(f0 - __half2float(h0)), __float2half(f1 - __half2float(h1)));
        __half2 l23(__float2half(f2 - __half2float(h2)), __float2half(f3 - __half2float(h3)));
        *(__half2*)(ahi + t0 + c) = u01;
        *(__half2*)(ahi + t1 + c) = u23;
        *(__half2*)(alo + t0 + c) = l01;
        *(__half2*)(alo + t1 + c) = l23;
    }
}

// ---- proj GEMM: fp16 2-term, lo in fp16 acc ----------------------------------
#define PTILE_E (128 * SROW)
#define PSTAGE_E (3 * PTILE_E)
#define PSMEM_SZ (2 * PSTAGE_E * 2)

__global__ __launch_bounds__(256, 1)
void gemm_proj(const __half* __restrict__ Ahi, const __half* __restrict__ Alo,
               const __half* __restrict__ Bh_g,
               const float* __restrict__ bias, float* __restrict__ C,
               int M, int N, int K)
{
    extern __shared__ __half smemh[];
    const int tid  = threadIdx.x;
    const int lane = tid & 31;
    const int wid  = tid >> 5;
    const int wm   = wid >> 2;
    const int wn   = wid & 3;
    const int tr   = lane >> 2;
    const int tc2  = (lane & 3) * 2;
    const int bm   = blockIdx.y * BM;
    const int bn   = blockIdx.x * BN;

    const uint32_t sbase = smem_u32(smemh);

    float acc[4][4][4];
    uint32_t lacc[4][4][2];
#pragma unroll
    for (int i = 0; i < 4; ++i)
#pragma unroll
        for (int j = 0; j < 4; ++j) {
#pragma unroll
            for (int r = 0; r < 4; ++r) acc[i][j][r] = 0.f;
            lacc[i][j][0] = 0u; lacc[i][j][1] = 0u;
        }

    const __half* srcs[3] = { Ahi, Alo, Bh_g };
    const int rowoff[3] = { bm, bm, bn };

    auto load_stage = [&](int s, int k0) {
        const uint32_t st = sbase + (uint32_t)(s * PSTAGE_E * 2);
#pragma unroll
        for (int t = 0; t < 3; ++t) {
#pragma unroll
            for (int g2 = 0; g2 < 2; ++g2) {
                const int g = tid + g2 * 256;
                const int row = g >> 2, part = g & 3;
                const uint32_t dst = st + (uint32_t)(t * PTILE_E + row * SROW + part * 8) * 2;
                const __half* src = srcs[t] + (size_t)(rowoff[t] + row) * K + k0 + part * 8;
                cp16(dst, src);
            }
        }
    };

    const int KCH = K / BK;
    load_stage(0, 0);
    CP_COMMIT();

    for (int c = 0; c < KCH; ++c) {
        if (c + 1 < KCH) { load_stage((c + 1) & 1, (c + 1) * BK); CP_COMMIT(); CP_WAIT(1); }
        else             { CP_WAIT(0); }
        __syncthreads();

        const __half* stg = smemh + (c & 1) * PSTAGE_E;
        const __half* Ah = stg;
        const __half* Al = stg + PTILE_E;
        const __half* Bh = stg + 2 * PTILE_E;

#pragma unroll
        for (int k0 = 0; k0 < BK; k0 += 16) {
            uint32_t ah[4][4], al[4][4], bh[4][2];
#pragma unroll
            for (int mi = 0; mi < 4; ++mi) {
                const int base = (wm * 64 + mi * 16 + tr) * SROW + k0 + tc2;
                ah[mi][0] = *(const uint32_t*)(Ah + base);
                ah[mi][1] = *(const uint32_t*)(Ah + base + 8 * SROW);
                ah[mi][2] = *(const uint32_t*)(Ah + base + 8);
                ah[mi][3] = *(const uint32_t*)(Ah + base + 8 * SROW + 8);
                al[mi][0] = *(const uint32_t*)(Al + base);
                al[mi][1] = *(const uint32_t*)(Al + base + 8 * SROW);
                al[mi][2] = *(const uint32_t*)(Al + base + 8);
                al[mi][3] = *(const uint32_t*)(Al + base + 8 * SROW + 8);
            }
#pragma unroll
            for (int ni = 0; ni < 4; ++ni) {
                const int base = (wn * 32 + ni * 8 + tr) * SROW + k0 + tc2;
                bh[ni][0] = *(const uint32_t*)(Bh + base);
                bh[ni][1] = *(const uint32_t*)(Bh + base + 8);
            }
#pragma unroll
            for (int mi = 0; mi < 4; ++mi)
#pragma unroll
                for (int ni = 0; ni < 4; ++ni)
                    mma_f16(acc[mi][ni], ah[mi][0], ah[mi][1], ah[mi][2], ah[mi][3],
                            bh[ni][0], bh[ni][1]);
#pragma unroll
            for (int mi = 0; mi < 4; ++mi)
#pragma unroll
                for (int ni = 0; ni < 4; ++ni)
                    mma_f16acc(lacc[mi][ni], al[mi][0], al[mi][1], al[mi][2], al[mi][3],
                               bh[ni][0], bh[ni][1]);
        }
        __syncthreads();
    }

#pragma unroll
    for (int mi = 0; mi < 4; ++mi) {
        const int r = bm + wm * 64 + mi * 16 + tr;
#pragma unroll
        for (int ni = 0; ni < 4; ++ni) {
            fold_lo(acc[mi][ni], lacc[mi][ni]);
            const int cidx = bn + wn * 32 + ni * 8 + tc2;
            const float b0 = bias[cidx], b1 = bias[cidx + 1];
            float2 v0 = make_float2(acc[mi][ni][0] + b0, acc[mi][ni][1] + b1);
            float2 v1 = make_float2(acc[mi][ni][2] + b0, acc[mi][ni][3] + b1);
            *(float2*)(C + (size_t)r * N + cidx)       = v0;
            *(float2*)(C + (size_t)(r + 8) * N + cidx) = v1;
        }
    }
}

// ---------------------------------------------------------------------------
extern "C" void kernel_launch(void* const* d_in, const int* in_sizes, int n_in,
                              void* d_out, int out_size)
{
    const float* x      = (const float*)d_in[0];
    const float* w_qkv  = (const float*)d_in[1];
    const float* b_qkv  = (const float*)d_in[2];
    const float* w_proj = (const float*)d_in[3];
    const float* b_proj = (const float*)d_in[4];
    float* out = (float*)d_out;

    __half *xhi, *xlo, *wq, *wph, *ahi, *alo;
    __half *qh, *ql, *kh, *kl, *vth, *vtl;
    cudaGetSymbolAddress((void**)&xhi, g_xhi);
    cudaGetSymbolAddress((void**)&xlo, g_xlo);
    cudaGetSymbolAddress((void**)&wq, g_wq);
    cudaGetSymbolAddress((void**)&wph, g_wph);
    cudaGetSymbolAddress((void**)&qh, g_qh);
    cudaGetSymbolAddress((void**)&ql, g_ql);
    cudaGetSymbolAddress((void**)&kh, g_kh);
    cudaGetSymbolAddress((void**)&kl, g_kl);
    cudaGetSymbolAddress((void**)&vth, g_vth);
    cudaGetSymbolAddress((void**)&vtl, g_vtl);
    cudaGetSymbolAddress((void**)&ahi, g_ahi);
    cudaGetSymbolAddress((void**)&alo, g_alo);

    cudaFuncSetAttribute(gemm_qkv,
                         cudaFuncAttributeMaxDynamicSharedMemorySize, QSMEM_SZ);
    cudaFuncSetAttribute(swa_tensor,
                         cudaFuncAttributeMaxDynamicSharedMemorySize, SWA_SMEM);
    cudaFuncSetAttribute(gemm_proj,
                         cudaFuncAttributeMaxDynamicSharedMemorySize, PSMEM_SZ);

    {
        int n4x = MTOT * D_MODEL / 4;
        int n4q = QKV_LD * D_MODEL / 4;
        int n4p = D_MODEL * D_MODEL / 4;
        split_f16<<<n4x / 256, 256>>>((const float4*)x, xhi, xlo, n4x);
        cvt_half<<<n4q / 256, 256>>>((const float4*)w_qkv, wq, n4q);
        cvt_half<<<n4p / 256, 256>>>((const float4*)w_proj, wph, n4p);
    }

    // 1) QKV projection -> per-head fp16 hi/lo Q,K + transposed V
    gemm_qkv<<<dim3(QKV_LD / BN, MTOT / BM), 256, QSMEM_SZ>>>(
        xhi, xlo, wq, b_qkv, qh, ql, kh, kl, vth, vtl);

    // 2) sliding-window attention -> fp16 hi/lo
    swa_tensor<<<dim3(SEQ / 64, BHTOT), 128, SWA_SMEM>>>(
        qh, ql, kh, kl, vth, vtl, ahi, alo);

    // 3) output projection
    gemm_proj<<<dim3(D_MODEL / BN, MTOT / BM), 256, PSMEM_SZ>>>(
        ahi, alo, wph, b_proj, out, MTOT, D_MODEL, D_MODEL);
}

// round 13
// speedup vs baseline: 1.4324x; 1.4324x over previous
#include <cuda_runtime.h>
#include <cuda_bf16.h>
#include <cuda_fp16.h>
#include <cstdint>

#define D_MODEL 1024
#define NHEADS  16
#define HDIM    64
#define WINDOW  256
#define BATCH   2
#define SEQ     2048
#define MTOT    (BATCH * SEQ)          /* 4096 */
#define QKV_LD  (3 * D_MODEL)          /* 3072 */
#define BHTOT   (BATCH * NHEADS)       /* 32 */

// ---- scratch --------------------------------------------------------------
__device__ __half        g_xf[(size_t)MTOT * D_MODEL];
__device__ __half        g_wq[(size_t)QKV_LD * D_MODEL];
__device__ __half        g_wph[(size_t)D_MODEL * D_MODEL];
// per-head Q/K: [bh][token][e]; V transposed: [bh][e][token]  (bf16 hi/lo)
__device__ __nv_bfloat16 g_qh[(size_t)BHTOT * SEQ * HDIM];
__device__ __nv_bfloat16 g_ql[(size_t)BHTOT * SEQ * HDIM];
__device__ __nv_bfloat16 g_kh[(size_t)BHTOT * SEQ * HDIM];
__device__ __nv_bfloat16 g_kl[(size_t)BHTOT * SEQ * HDIM];
__device__ __nv_bfloat16 g_vth[(size_t)BHTOT * HDIM * SEQ];
__device__ __nv_bfloat16 g_vtl[(size_t)BHTOT * HDIM * SEQ];
// attention out, fp16 hi/lo for proj
__device__ __half        g_ahi[(size_t)MTOT * D_MODEL];
__device__ __half        g_alo[(size_t)MTOT * D_MODEL];

// ---- PTX helpers ------------------------------------------------------------
__device__ __forceinline__ uint32_t smem_u32(const void* p) {
    uint32_t a;
    asm("{ .reg .u64 t; cvta.to.shared.u64 t, %1; cvt.u32.u64 %0, t; }" : "=r"(a) : "l"(p));
    return a;
}
__device__ __forceinline__ void cp16(uint32_t dst, const void* src) {
    asm volatile("cp.async.cg.shared.global [%0], [%1], 16;" :: "r"(dst), "l"(src));
}
#define CP_COMMIT()  asm volatile("cp.async.commit_group;" ::: "memory")
#define CP_WAIT(n)   asm volatile("cp.async.wait_group %0;" :: "n"(n) : "memory")

__device__ __forceinline__ void mma_bf16(float* d, uint32_t a0, uint32_t a1,
                                         uint32_t a2, uint32_t a3,
                                         uint32_t b0, uint32_t b1) {
    asm("mma.sync.aligned.m16n8k16.row.col.f32.bf16.bf16.f32 "
        "{%0,%1,%2,%3}, {%4,%5,%6,%7}, {%8,%9}, {%0,%1,%2,%3};"
        : "+f"(d[0]), "+f"(d[1]), "+f"(d[2]), "+f"(d[3])
        : "r"(a0), "r"(a1), "r"(a2), "r"(a3), "r"(b0), "r"(b1));
}
__device__ __forceinline__ void mma_f16(float* d, uint32_t a0, uint32_t a1,
                                        uint32_t a2, uint32_t a3,
                                        uint32_t b0, uint32_t b1) {
    asm("mma.sync.aligned.m16n8k16.row.col.f32.f16.f16.f32 "
        "{%0,%1,%2,%3}, {%4,%5,%6,%7}, {%8,%9}, {%0,%1,%2,%3};"
        : "+f"(d[0]), "+f"(d[1]), "+f"(d[2]), "+f"(d[3])
        : "r"(a0), "r"(a1), "r"(a2), "r"(a3), "r"(b0), "r"(b1));
}
__device__ __forceinline__ uint32_t pack_bf16(float a, float b) {
    __nv_bfloat162 t(__float2bfloat16(a), __float2bfloat16(b));
    return *(uint32_t*)&t;
}

// ---- splits ------------------------------------------------------------------
__global__ __launch_bounds__(256)
void split_f16(const float4* __restrict__ in, __half* __restrict__ hi,
               __half* __restrict__ lo, int n4)
{
    int i = blockIdx.x * 256 + threadIdx.x;
    if (i >= n4) return;
    float4 v = in[i];
    __half h0 = __float2half(v.x), h1 = __float2half(v.y);
    __half h2 = __float2half(v.z), h3 = __float2half(v.w);
    __half2* hp = (__half2*)(hi + i * 4);
    __half2* lp = (__half2*)(lo + i * 4);
    hp[0] = __half2(h0, h1);
    hp[1] = __half2(h2, h3);
    lp[0] = __half2(__float2half(v.x - __half2float(h0)),
                    __float2half(v.y - __half2float(h1)));
    lp[1] = __half2(__float2half(v.z - __half2float(h2)),
                    __float2half(v.w - __half2float(h3)));
}
__global__ __launch_bounds__(256)
void cvt_half(const float4* __restrict__ in, __half* __restrict__ out, int n4)
{
    int i = blockIdx.x * 256 + threadIdx.x;
    if (i >= n4) return;
    float4 v = in[i];
    __half2* op = (__half2*)(out + i * 4);
    op[0] = __half2(__float2half(v.x), __float2half(v.y));
    op[1] = __half2(__float2half(v.z), __float2half(v.w));
}

// ---- QKV GEMM: fp16 1-term; epilogue writes bf16 Q/K hi/lo + transposed V ----
#define BM 128
#define BN 128
#define BK 32
#define SROW 40
#define TILE_E (128 * SROW)
#define QSTAGE_E (2 * TILE_E)
#define QSMEM_SZ 66048                  /* epilogue V stage needs 128*129*4 */

__global__ __launch_bounds__(256, 2)
void gemm_qkv(const __half* __restrict__ A, const __half* __restrict__ W,
              const float* __restrict__ bias,
              __nv_bfloat16* __restrict__ qh_o, __nv_bfloat16* __restrict__ ql_o,
              __nv_bfloat16* __restrict__ kh_o, __nv_bfloat16* __restrict__ kl_o,
              __nv_bfloat16* __restrict__ vth_o, __nv_bfloat16* __restrict__ vtl_o)
{
    extern __shared__ __half smemh[];
    const int K = D_MODEL;
    const int tid  = threadIdx.x;
    const int lane = tid & 31;
    const int wid  = tid >> 5;
    const int wm   = wid >> 2;
    const int wn   = wid & 3;
    const int tr   = lane >> 2;
    const int tc2  = (lane & 3) * 2;
    const int bm   = blockIdx.y * BM;
    const int bn   = blockIdx.x * BN;

    const uint32_t sbase = smem_u32(smemh);

    float acc[4][4][4];
#pragma unroll
    for (int i = 0; i < 4; ++i)
#pragma unroll
        for (int j = 0; j < 4; ++j)
#pragma unroll
            for (int r = 0; r < 4; ++r) acc[i][j][r] = 0.f;

    const __half* srcs[2] = { A, W };
    const int rowoff[2] = { bm, bn };

    auto load_stage = [&](int s, int k0) {
        const uint32_t st = sbase + (uint32_t)(s * QSTAGE_E * 2);
#pragma unroll
        for (int t = 0; t < 2; ++t) {
#pragma unroll
            for (int g2 = 0; g2 < 2; ++g2) {
                const int g = tid + g2 * 256;
                const int row = g >> 2, part = g & 3;
                const uint32_t dst = st + (uint32_t)(t * TILE_E + row * SROW + part * 8) * 2;
                const __half* src = srcs[t] + (size_t)(rowoff[t] + row) * K + k0 + part * 8;
                cp16(dst, src);
            }
        }
    };

    const int KCH = K / BK;
    load_stage(0, 0);
    CP_COMMIT();

    for (int c = 0; c < KCH; ++c) {
        if (c + 1 < KCH) { load_stage((c + 1) & 1, (c + 1) * BK); CP_COMMIT(); CP_WAIT(1); }
        else             { CP_WAIT(0); }
        __syncthreads();

        const __half* stg = smemh + (c & 1) * QSTAGE_E;
        const __half* Ah = stg;
        const __half* Bh = stg + TILE_E;

#pragma unroll
        for (int k0 = 0; k0 < BK; k0 += 16) {
            uint32_t ah[4][4], bh[4][2];
#pragma unroll
            for (int mi = 0; mi < 4; ++mi) {
                const int base = (wm * 64 + mi * 16 + tr) * SROW + k0 + tc2;
                ah[mi][0] = *(const uint32_t*)(Ah + base);
                ah[mi][1] = *(const uint32_t*)(Ah + base + 8 * SROW);
                ah[mi][2] = *(const uint32_t*)(Ah + base + 8);
                ah[mi][3] = *(const uint32_t*)(Ah + base + 8 * SROW + 8);
            }
#pragma unroll
            for (int ni = 0; ni < 4; ++ni) {
                const int base = (wn * 32 + ni * 8 + tr) * SROW + k0 + tc2;
                bh[ni][0] = *(const uint32_t*)(Bh + base);
                bh[ni][1] = *(const uint32_t*)(Bh + base + 8);
            }
#pragma unroll
            for (int mi = 0; mi < 4; ++mi)
#pragma unroll
                for (int ni = 0; ni < 4; ++ni)
                    mma_f16(acc[mi][ni], ah[mi][0], ah[mi][1], ah[mi][2], ah[mi][3],
                            bh[ni][0], bh[ni][1]);
        }
        __syncthreads();
    }

    // ---- epilogue: bf16 hi/lo Q/K + transposed V ----
    if (bn < 2 * D_MODEL) {
        __nv_bfloat16* H = (bn < D_MODEL) ? qh_o : kh_o;
        __nv_bfloat16* L = (bn < D_MODEL) ? ql_o : kl_o;
        const int roff = (bn < D_MODEL) ? bn : bn - D_MODEL;
#pragma unroll
        for (int mi = 0; mi < 4; ++mi) {
            const int r = bm + wm * 64 + mi * 16 + tr;
            const int b = r >> 11, row = r & 2047;
#pragma unroll
            for (int ni = 0; ni < 4; ++ni) {
                const int cl = wn * 32 + ni * 8 + tc2;
                const float b0 = bias[bn + cl], b1 = bias[bn + cl + 1];
                const int cg = roff + cl, hh = cg >> 6, e = cg & 63;
                const size_t base =
                    (((size_t)b * NHEADS + hh) * SEQ + row) * HDIM + e;
                float v0 = acc[mi][ni][0] + b0, v1 = acc[mi][ni][1] + b1;
                float v2 = acc[mi][ni][2] + b0, v3 = acc[mi][ni][3] + b1;
                __nv_bfloat16 h0 = __float2bfloat16(v0), h1 = __float2bfloat16(v1);
                __nv_bfloat16 h2 = __float2bfloat16(v2), h3 = __float2bfloat16(v3);
                __nv_bfloat162 u01(h0, h1), u23(h2, h3);
                *(uint32_t*)(H + base) = *(uint32_t*)&u01;
                *(uint32_t*)(L + base) = pack_bf16(v0 - __bfloat162float(h0),
                                                   v1 - __bfloat162float(h1));
                *(uint32_t*)(H + base + 8 * HDIM) = *(uint32_t*)&u23;
                *(uint32_t*)(L + base + 8 * HDIM) = pack_bf16(v2 - __bfloat162float(h2),
                                                              v3 - __bfloat162float(h3));
            }
        }
    } else {
        float* sf = (float*)smemh;
#pragma unroll
        for (int mi = 0; mi < 4; ++mi) {
            const int r0 = wm * 64 + mi * 16 + tr;
#pragma unroll
            for (int ni = 0; ni < 4; ++ni) {
                const int cl = wn * 32 + ni * 8 + tc2;
                const float b0 = bias[bn + cl], b1 = bias[bn + cl + 1];
                sf[r0 * 129 + cl]           = acc[mi][ni][0] + b0;
                sf[r0 * 129 + cl + 1]       = acc[mi][ni][1] + b1;
                sf[(r0 + 8) * 129 + cl]     = acc[mi][ni][2] + b0;
                sf[(r0 + 8) * 129 + cl + 1] = acc[mi][ni][3] + b1;
            }
        }
        __syncthreads();
        for (int idx = tid; idx < 128 * 64; idx += 256) {
            const int el = idx >> 6, rp = idx & 63;
            const float f0 = sf[(2 * rp) * 129 + el];
            const float f1 = sf[(2 * rp + 1) * 129 + el];
            const int cg = bn - 2 * D_MODEL + el, hh = cg >> 6, e = cg & 63;
            const int rg = bm + 2 * rp, b = rg >> 11, row = rg & 2047;
            const size_t base = (((size_t)b * NHEADS + hh) * HDIM + e) * SEQ + row;
            __nv_bfloat16 h0 = __float2bfloat16(f0), h1 = __float2bfloat16(f1);
            __nv_bfloat162 u(h0, h1);
            *(uint32_t*)(vth_o + base) = *(uint32_t*)&u;
            *(uint32_t*)(vtl_o + base) = pack_bf16(f0 - __bfloat162float(h0),
                                                   f1 - __bfloat162float(h1));
        }
    }
}

// ---- swa: bf16x3, pure cp.async fill (identical to the 330us build) ----------
#define SROW2 72
#define QT (64 * SROW2)
#define SWA_SMEM (10 * QT * 2)

__global__ __launch_bounds__(128, 2)
void swa_tensor(const __nv_bfloat16* __restrict__ qh_g, const __nv_bfloat16* __restrict__ ql_g,
                const __nv_bfloat16* __restrict__ kh_g, const __nv_bfloat16* __restrict__ kl_g,
                const __nv_bfloat16* __restrict__ vth_g, const __nv_bfloat16* __restrict__ vtl_g,
                __half* __restrict__ ahi, __half* __restrict__ alo)
{
    extern __shared__ __nv_bfloat16 sm[];
    const int tid = threadIdx.x, lane = tid & 31, w = tid >> 5;
    const int bh = blockIdx.y;
    const int q0 = blockIdx.x * 64;
    const int tr = lane >> 2, tc2 = (lane & 3) * 2;

    const uint32_t sQh = smem_u32(sm);
    const uint32_t sQl = sQh + QT * 2;

    const size_t qkbase = (size_t)bh * SEQ * HDIM;
    const size_t vbase  = (size_t)bh * HDIM * SEQ;

    auto load_qk = [&](uint32_t sdst, const __nv_bfloat16* src) {
#pragma unroll
        for (int it = 0; it < 4; ++it) {
            const int g = it * 128 + tid;
            const int row = g >> 3, ch = g & 7;
            cp16(sdst + (uint32_t)(row * SROW2 + ch * 8) * 2,
                 src + (size_t)row * HDIM + ch * 8);
        }
    };
    auto load_vt = [&](uint32_t sdst, const __nv_bfloat16* src) {
#pragma unroll
        for (int it = 0; it < 4; ++it) {
            const int g = it * 128 + tid;
            const int row = g >> 3, ch = g & 7;
            cp16(sdst + (uint32_t)(row * SROW2 + ch * 8) * 2,
                 src + (size_t)row * SEQ + ch * 8);
        }
    };
    auto issue_stage = [&](int s, int j0) {
        const uint32_t st = sQh + (uint32_t)((2 + 4 * s) * QT) * 2;
        load_qk(st,              kh_g + qkbase + (size_t)j0 * HDIM);
        load_qk(st + QT * 2,     kl_g + qkbase + (size_t)j0 * HDIM);
        load_vt(st + 2 * QT * 2, vth_g + vbase + j0);
        load_vt(st + 3 * QT * 2, vtl_g + vbase + j0);
    };

    const int kt0 = max(0, (int)blockIdx.x - 4);
    const int kt1 = blockIdx.x;

    load_qk(sQh, qh_g + qkbase + (size_t)q0 * HDIM);
    load_qk(sQl, ql_g + qkbase + (size_t)q0 * HDIM);
    issue_stage(0, kt0 * 64);
    CP_COMMIT();

    uint32_t qh[4][4], ql[4][4];
    float o[8][4];
#pragma unroll
    for (int ni = 0; ni < 8; ++ni)
#pragma unroll
        for (int j = 0; j < 4; ++j) o[ni][j] = 0.f;
    float m0 = -1e30f, m1 = -1e30f, l0 = 0.f, l1 = 0.f;
    const int i0 = q0 + w * 16 + tr;
    const int i1 = i0 + 8;

    for (int kt = kt0; kt <= kt1; ++kt) {
        const int s = (kt - kt0) & 1;
        if (kt + 1 <= kt1) { issue_stage(s ^ 1, (kt + 1) * 64); CP_COMMIT(); CP_WAIT(1); }
        else               { CP_WAIT(0); }
        __syncthreads();

        if (kt == kt0) {
            const __nv_bfloat16* Qh = sm;
            const __nv_bfloat16* Ql = sm + QT;
#pragma unroll
            for (int ks = 0; ks < 4; ++ks) {
                const int base = (w * 16 + tr) * SROW2 + ks * 16 + tc2;
                qh[ks][0] = *(const uint32_t*)(Qh + base);
                qh[ks][1] = *(const uint32_t*)(Qh + base + 8 * SROW2);
                qh[ks][2] = *(const uint32_t*)(Qh + base + 8);
                qh[ks][3] = *(const uint32_t*)(Qh + base + 8 * SROW2 + 8);
                ql[ks][0] = *(const uint32_t*)(Ql + base);
                ql[ks][1] = *(const uint32_t*)(Ql + base + 8 * SROW2);
                ql[ks][2] = *(const uint32_t*)(Ql + base + 8);
                ql[ks][3] = *(const uint32_t*)(Ql + base + 8 * SROW2 + 8);
            }
        }

        const __nv_bfloat16* Kh  = sm + (2 + 4 * s) * QT;
        const __nv_bfloat16* Kl  = Kh + QT;
        const __nv_bfloat16* Vth = Kh + 2 * QT;
        const __nv_bfloat16* Vtl = Kh + 3 * QT;
        const int j0 = kt * 64;

        float sacc[8][4];
#pragma unroll
        for (int ni = 0; ni < 8; ++ni)
#pragma unroll
            for (int j = 0; j < 4; ++j) sacc[ni][j] = 0.f;
#pragma unroll
        for (int ks = 0; ks < 4; ++ks) {
            uint32_t kb[8][2], klr[8][2];
#pragma unroll
            for (int ni = 0; ni < 8; ++ni) {
                const int base = (ni * 8 + tr) * SROW2 + ks * 16 + tc2;
                kb[ni][0]  = *(const uint32_t*)(Kh + base);
                kb[ni][1]  = *(const uint32_t*)(Kh + base + 8);
                klr[ni][0] = *(const uint32_t*)(Kl + base);
                klr[ni][1] = *(const uint32_t*)(Kl + base + 8);
            }
#pragma unroll
            for (int ni = 0; ni < 8; ++ni)
                mma_bf16(sacc[ni], qh[ks][0], qh[ks][1], qh[ks][2], qh[ks][3],
                         kb[ni][0], kb[ni][1]);
#pragma unroll
            for (int ni = 0; ni < 8; ++ni)
                mma_bf16(sacc[ni], ql[ks][0], ql[ks][1], ql[ks][2], ql[ks][3],
                         kb[ni][0], kb[ni][1]);
#pragma unroll
            for (int ni = 0; ni < 8; ++ni)
                mma_bf16(sacc[ni], qh[ks][0], qh[ks][1], qh[ks][2], qh[ks][3],
                         klr[ni][0], klr[ni][1]);
        }

        float tmax0 = -1e30f, tmax1 = -1e30f;
#pragma unroll
        for (int ni = 0; ni < 8; ++ni) {
            const int ja = j0 + ni * 8 + tc2, jb = ja + 1;
            sacc[ni][0] = (ja <= i0 && (i0 - ja) < WINDOW) ? sacc[ni][0] * 0.125f : -1e30f;
            sacc[ni][1] = (jb <= i0 && (i0 - jb) < WINDOW) ? sacc[ni][1] * 0.125f : -1e30f;
            sacc[ni][2] = (ja <= i1 && (i1 - ja) < WINDOW) ? sacc[ni][2] * 0.125f : -1e30f;
            sacc[ni][3] = (jb <= i1 && (i1 - jb) < WINDOW) ? sacc[ni][3] * 0.125f : -1e30f;
            tmax0 = fmaxf(tmax0, fmaxf(sacc[ni][0], sacc[ni][1]));
            tmax1 = fmaxf(tmax1, fmaxf(sacc[ni][2], sacc[ni][3]));
        }
        tmax0 = fmaxf(tmax0, __shfl_xor_sync(0xffffffff, tmax0, 1));
        tmax0 = fmaxf(tmax0, __shfl_xor_sync(0xffffffff, tmax0, 2));
        tmax1 = fmaxf(tmax1, __shfl_xor_sync(0xffffffff, tmax1, 1));
        tmax1 = fmaxf(tmax1, __shfl_xor_sync(0xffffffff, tmax1, 2));

        const float mn0 = fmaxf(m0, tmax0), mn1 = fmaxf(m1, tmax1);
        const float sc0 = __expf(m0 - mn0), sc1 = __expf(m1 - mn1);
        m0 = mn0; m1 = mn1;

        float rs0 = 0.f, rs1 = 0.f;
        uint32_t ph[8][2], pl[8][2];
#pragma unroll
        for (int ni = 0; ni < 8; ++ni) {
            float p0 = __expf(sacc[ni][0] - mn0);
            float p1 = __expf(sacc[ni][1] - mn0);
            float p2 = __expf(sacc[ni][2] - mn1);
            float p3 = __expf(sacc[ni][3] - mn1);
            rs0 += p0 + p1; rs1 += p2 + p3;
            __nv_bfloat16 b0 = __float2bfloat16(p0), b1 = __float2bfloat16(p1);
            __nv_bfloat16 b2 = __float2bfloat16(p2), b3 = __float2bfloat16(p3);
            __nv_bfloat162 t01(b0, b1), t23(b2, b3);
            ph[ni][0] = *(uint32_t*)&t01;
            ph[ni][1] = *(uint32_t*)&t23;
            pl[ni][0] = pack_bf16(p0 - __bfloat162float(b0), p1 - __bfloat162float(b1));
            pl[ni][1] = pack_bf16(p2 - __bfloat162float(b2), p3 - __bfloat162float(b3));
        }
        rs0 += __shfl_xor_sync(0xffffffff, rs0, 1);
        rs0 += __shfl_xor_sync(0xffffffff, rs0, 2);
        rs1 += __shfl_xor_sync(0xffffffff, rs1, 1);
        rs1 += __shfl_xor_sync(0xffffffff, rs1, 2);
        l0 = l0 * sc0 + rs0;
        l1 = l1 * sc1 + rs1;

#pragma unroll
        for (int ni = 0; ni < 8; ++ni) {
            o[ni][0] *= sc0; o[ni][1] *= sc0;
            o[ni][2] *= sc1; o[ni][3] *= sc1;
        }

#pragma unroll
        for (int ks = 0; ks < 4; ++ks) {
            uint32_t vb[8][2], vl[8][2];
#pragma unroll
            for (int ni = 0; ni < 8; ++ni) {
                const int base = (ni * 8 + tr) * SROW2 + ks * 16 + tc2;
                vb[ni][0] = *(const uint32_t*)(Vth + base);
                vb[ni][1] = *(const uint32_t*)(Vth + base + 8);
                vl[ni][0] = *(const uint32_t*)(Vtl + base);
                vl[ni][1] = *(const uint32_t*)(Vtl + base + 8);
            }
#pragma unroll
            for (int ni = 0; ni < 8; ++ni)
                mma_bf16(o[ni], ph[2*ks][0], ph[2*ks][1], ph[2*ks+1][0], ph[2*ks+1][1],
                         vb[ni][0], vb[ni][1]);
#pragma unroll
            for (int ni = 0; ni < 8; ++ni)
                mma_bf16(o[ni], pl[2*ks][0], pl[2*ks][1], pl[2*ks+1][0], pl[2*ks+1][1],
                         vb[ni][0], vb[ni][1]);
#pragma unroll
            for (int ni = 0; ni < 8; ++ni)
                mma_bf16(o[ni], ph[2*ks][0], ph[2*ks][1], ph[2*ks+1][0], ph[2*ks+1][1],
                         vl[ni][0], vl[ni][1]);
        }
        __syncthreads();
    }

    const int b = bh >> 4, h = bh & 15;
    const float inv0 = 1.f / l0, inv1 = 1.f / l1;
    const size_t t0 = (size_t)(b * SEQ + i0) * D_MODEL + (size_t)h * HDIM;
    const size_t t1 = (size_t)(b * SEQ + i1) * D_MODEL + (size_t)h * HDIM;
#pragma unroll
    for (int ni = 0; ni < 8; ++ni) {
        const int c = ni * 8 + tc2;
        float f0 = o[ni][0] * inv0, f1 = o[ni][1] * inv0;
        float f2 = o[ni][2] * inv1, f3 = o[ni][3] * inv1;
        __half h0 = __float2half(f0), h1 = __float2half(f1);
        __half h2 = __float2half(f2), h3 = __float2half(f3);
        __half2 u01(h0, h1), u23(h2, h3);
        __half2 l01(__float2half(f0 - __half2float(h0)), __float2half(f1 - __half2float(h1)));
        __half2 l23(__float2half(f2 - __half2float(h2)), __float2half(f3 - __half2float(h3)));
        *(__half2*)(ahi + t0 + c) = u01;
        *(__half2*)(ahi + t1 + c) = u23;
        *(__half2*)(alo + t0 + c) = l01;
        *(__half2*)(alo + t1 + c) = l23;
    }
}

// ---- proj GEMM: fp16 2-term (identical to the 330us build) -------------------
#define PTILE_E (128 * SROW)
#define PSTAGE_E (3 * PTILE_E)
#define PSMEM_SZ (2 * PSTAGE_E * 2)

__global__ __launch_bounds__(256, 2)
void gemm_proj(const __half* __restrict__ Ahi, const __half* __restrict__ Alo,
               const __half* __restrict__ Bh_g,
               const float* __restrict__ bias, float* __restrict__ C,
               int M, int N, int K)
{
    extern __shared__ __half smemh[];
    const int tid  = threadIdx.x;
    const int lane = tid & 31;
    const int wid  = tid >> 5;
    const int wm   = wid >> 2;
    const int wn   = wid & 3;
    const int tr   = lane >> 2;
    const int tc2  = (lane & 3) * 2;
    const int bm   = blockIdx.y * BM;
    const int bn   = blockIdx.x * BN;

    const uint32_t sbase = smem_u32(smemh);

    float acc[4][4][4];
#pragma unroll
    for (int i = 0; i < 4; ++i)
#pragma unroll
        for (int j = 0; j < 4; ++j)
#pragma unroll
            for (int r = 0; r < 4; ++r) acc[i][j][r] = 0.f;

    const __half* srcs[3] = { Ahi, Alo, Bh_g };
    const int rowoff[3] = { bm, bm, bn };

    auto load_stage = [&](int s, int k0) {
        const uint32_t st = sbase + (uint32_t)(s * PSTAGE_E * 2);
#pragma unroll
        for (int t = 0; t < 3; ++t) {
#pragma unroll
            for (int g2 = 0; g2 < 2; ++g2) {
                const int g = tid + g2 * 256;
                const int row = g >> 2, part = g & 3;
                const uint32_t dst = st + (uint32_t)(t * PTILE_E + row * SROW + part * 8) * 2;
                const __half* src = srcs[t] + (size_t)(rowoff[t] + row) * K + k0 + part * 8;
                cp16(dst, src);
            }
        }
    };

    const int KCH = K / BK;
    load_stage(0, 0);
    CP_COMMIT();

    for (int c = 0; c < KCH; ++c) {
        if (c + 1 < KCH) { load_stage((c + 1) & 1, (c + 1) * BK); CP_COMMIT(); CP_WAIT(1); }
        else             { CP_WAIT(0); }
        __syncthreads();

        const __half* stg = smemh + (c & 1) * PSTAGE_E;
        const __half* Ah = stg;
        const __half* Al = stg + PTILE_E;
        const __half* Bh = stg + 2 * PTILE_E;

#pragma unroll
        for (int k0 = 0; k0 < BK; k0 += 16) {
            uint32_t ah[4][4], al[4][4], bh[4][2];
#pragma unroll
            for (int mi = 0; mi < 4; ++mi) {
                const int base = (wm * 64 + mi * 16 + tr) * SROW + k0 + tc2;
                ah[mi][0] = *(const uint32_t*)(Ah + base);
                ah[mi][1] = *(const uint32_t*)(Ah + base + 8 * SROW);
                ah[mi][2] = *(const uint32_t*)(Ah + base + 8);
                ah[mi][3] = *(const uint32_t*)(Ah + base + 8 * SROW + 8);
                al[mi][0] = *(const uint32_t*)(Al + base);
                al[mi][1] = *(const uint32_t*)(Al + base + 8 * SROW);
                al[mi][2] = *(const uint32_t*)(Al + base + 8);
                al[mi][3] = *(const uint32_t*)(Al + base + 8 * SROW + 8);
            }
#pragma unroll
            for (int ni = 0; ni < 4; ++ni) {
                const int base = (wn * 32 + ni * 8 + tr) * SROW + k0 + tc2;
                bh[ni][0] = *(const uint32_t*)(Bh + base);
                bh[ni][1] = *(const uint32_t*)(Bh + base + 8);
            }
#pragma unroll
            for (int mi = 0; mi < 4; ++mi)
#pragma unroll
                for (int ni = 0; ni < 4; ++ni)
                    mma_f16(acc[mi][ni], ah[mi][0], ah[mi][1], ah[mi][2], ah[mi][3],
                            bh[ni][0], bh[ni][1]);
#pragma unroll
            for (int mi = 0; mi < 4; ++mi)
#pragma unroll
                for (int ni = 0; ni < 4; ++ni)
                    mma_f16(acc[mi][ni], al[mi][0], al[mi][1], al[mi][2], al[mi][3],
                            bh[ni][0], bh[ni][1]);
        }
        __syncthreads();
    }

#pragma unroll
    for (int mi = 0; mi < 4; ++mi) {
        const int r = bm + wm * 64 + mi * 16 + tr;
#pragma unroll
        for (int ni = 0; ni < 4; ++ni) {
            const int cidx = bn + wn * 32 + ni * 8 + tc2;
            const float b0 = bias[cidx], b1 = bias[cidx + 1];
            float2 v0 = make_float2(acc[mi][ni][0] + b0, acc[mi][ni][1] + b1);
            float2 v1 = make_float2(acc[mi][ni][2] + b0, acc[mi][ni][3] + b1);
            *(float2*)(C + (size_t)r * N + cidx)       = v0;
            *(float2*)(C + (size_t)(r + 8) * N + cidx) = v1;
        }
    }
}

// ---------------------------------------------------------------------------
extern "C" void kernel_launch(void* const* d_in, const int* in_sizes, int n_in,
                              void* d_out, int out_size)
{
    const float* x      = (const float*)d_in[0];
    const float* w_qkv  = (const float*)d_in[1];
    const float* b_qkv  = (const float*)d_in[2];
    const float* w_proj = (const float*)d_in[3];
    const float* b_proj = (const float*)d_in[4];
    float* out = (float*)d_out;

    __half *xf, *wq, *wph, *ahi, *alo;
    __nv_bfloat16 *qh, *ql, *kh, *kl, *vth, *vtl;
    cudaGetSymbolAddress((void**)&xf, g_xf);
    cudaGetSymbolAddress((void**)&wq, g_wq);
    cudaGetSymbolAddress((void**)&wph, g_wph);
    cudaGetSymbolAddress((void**)&qh, g_qh);
    cudaGetSymbolAddress((void**)&ql, g_ql);
    cudaGetSymbolAddress((void**)&kh, g_kh);
    cudaGetSymbolAddress((void**)&kl, g_kl);
    cudaGetSymbolAddress((void**)&vth, g_vth);
    cudaGetSymbolAddress((void**)&vtl, g_vtl);
    cudaGetSymbolAddress((void**)&ahi, g_ahi);
    cudaGetSymbolAddress((void**)&alo, g_alo);

    cudaFuncSetAttribute(gemm_qkv,
                         cudaFuncAttributeMaxDynamicSharedMemorySize, QSMEM_SZ);
    cudaFuncSetAttribute(swa_tensor,
                         cudaFuncAttributeMaxDynamicSharedMemorySize, SWA_SMEM);
    cudaFuncSetAttribute(gemm_proj,
                         cudaFuncAttributeMaxDynamicSharedMemorySize, PSMEM_SZ);

    {
        int n4x = MTOT * D_MODEL / 4;
        int n4q = QKV_LD * D_MODEL / 4;
        int n4p = D_MODEL * D_MODEL / 4;
        cvt_half<<<n4x / 256, 256>>>((const float4*)x, xf, n4x);
        cvt_half<<<n4q / 256, 256>>>((const float4*)w_qkv, wq, n4q);
        cvt_half<<<n4p / 256, 256>>>((const float4*)w_proj, wph, n4p);
    }

    // 1) QKV projection (fp16 1-term) -> per-head bf16 hi/lo Q,K + transposed V
    gemm_qkv<<<dim3(QKV_LD / BN, MTOT / BM), 256, QSMEM_SZ>>>(
        xf, wq, b_qkv, qh, ql, kh, kl, vth, vtl);

    // 2) sliding-window attention (bf16x3) -> fp16 hi/lo
    swa_tensor<<<dim3(SEQ / 64, BHTOT), 128, SWA_SMEM>>>(
        qh, ql, kh, kl, vth, vtl, ahi, alo);

    // 3) output projection (fp16 2-term)
    gemm_proj<<<dim3(D_MODEL / BN, MTOT / BM), 256, PSMEM_SZ>>>(
        ahi, alo, wph, b_proj, out, MTOT, D_MODEL, D_MODEL);
}

// round 14
// speedup vs baseline: 1.6026x; 1.1188x over previous
#include <cuda_runtime.h>
#include <cuda_fp16.h>
#include <cstdint>

#define D_MODEL 1024
#define NHEADS  16
#define HDIM    64
#define WINDOW  256
#define BATCH   2
#define SEQ     2048
#define MTOT    (BATCH * SEQ)          /* 4096 */
#define QKV_LD  (3 * D_MODEL)          /* 3072 */
#define BHTOT   (BATCH * NHEADS)       /* 32 */

// ---- scratch --------------------------------------------------------------
__device__ __half g_xf[(size_t)MTOT * D_MODEL];
__device__ __half g_wq[(size_t)QKV_LD * D_MODEL];
__device__ __half g_wph[(size_t)D_MODEL * D_MODEL];
// per-head Q/K: [bh][token][e]; V transposed: [bh][e][token]  (plain fp16)
__device__ __half g_q[(size_t)BHTOT * SEQ * HDIM];
__device__ __half g_k[(size_t)BHTOT * SEQ * HDIM];
__device__ __half g_vt[(size_t)BHTOT * HDIM * SEQ];
// attention out, fp16 hi/lo for proj
__device__ __half g_ahi[(size_t)MTOT * D_MODEL];
__device__ __half g_alo[(size_t)MTOT * D_MODEL];

// ---- PTX helpers ------------------------------------------------------------
__device__ __forceinline__ uint32_t smem_u32(const void* p) {
    uint32_t a;
    asm("{ .reg .u64 t; cvta.to.shared.u64 t, %1; cvt.u32.u64 %0, t; }" : "=r"(a) : "l"(p));
    return a;
}
__device__ __forceinline__ void cp16(uint32_t dst, const void* src) {
    asm volatile("cp.async.cg.shared.global [%0], [%1], 16;" :: "r"(dst), "l"(src));
}
#define CP_COMMIT()  asm volatile("cp.async.commit_group;" ::: "memory")
#define CP_WAIT(n)   asm volatile("cp.async.wait_group %0;" :: "n"(n) : "memory")

__device__ __forceinline__ void mma_f16(float* d, uint32_t a0, uint32_t a1,
                                        uint32_t a2, uint32_t a3,
                                        uint32_t b0, uint32_t b1) {
    asm("mma.sync.aligned.m16n8k16.row.col.f32.f16.f16.f32 "
        "{%0,%1,%2,%3}, {%4,%5,%6,%7}, {%8,%9}, {%0,%1,%2,%3};"
        : "+f"(d[0]), "+f"(d[1]), "+f"(d[2]), "+f"(d[3])
        : "r"(a0), "r"(a1), "r"(a2), "r"(a3), "r"(b0), "r"(b1));
}

// ---- fp32 -> fp16 convert -----------------------------------------------------
__global__ __launch_bounds__(256)
void cvt_half(const float4* __restrict__ in, __half* __restrict__ out, int n4)
{
    int i = blockIdx.x * 256 + threadIdx.x;
    if (i >= n4) return;
    float4 v = in[i];
    __half2* op = (__half2*)(out + i * 4);
    op[0] = __half2(__float2half(v.x), __float2half(v.y));
    op[1] = __half2(__float2half(v.z), __float2half(v.w));
}

// ---- QKV GEMM: fp16 1-term; epilogue writes fp16 Q/K + transposed V ----------
#define BM 128
#define BN 128
#define BK 32
#define SROW 40
#define TILE_E (128 * SROW)
#define QSTAGE_E (2 * TILE_E)
#define QSMEM_SZ 66048                  /* epilogue V stage needs 128*129*4 */

__global__ __launch_bounds__(256, 2)
void gemm_qkv(const __half* __restrict__ A, const __half* __restrict__ W,
              const float* __restrict__ bias,
              __half* __restrict__ q_o, __half* __restrict__ k_o,
              __half* __restrict__ vt_o)
{
    extern __shared__ __half smemh[];
    const int K = D_MODEL;
    const int tid  = threadIdx.x;
    const int lane = tid & 31;
    const int wid  = tid >> 5;
    const int wm   = wid >> 2;
    const int wn   = wid & 3;
    const int tr   = lane >> 2;
    const int tc2  = (lane & 3) * 2;
    const int bm   = blockIdx.y * BM;
    const int bn   = blockIdx.x * BN;

    const uint32_t sbase = smem_u32(smemh);

    float acc[4][4][4];
#pragma unroll
    for (int i = 0; i < 4; ++i)
#pragma unroll
        for (int j = 0; j < 4; ++j)
#pragma unroll
            for (int r = 0; r < 4; ++r) acc[i][j][r] = 0.f;

    const __half* srcs[2] = { A, W };
    const int rowoff[2] = { bm, bn };

    auto load_stage = [&](int s, int k0) {
        const uint32_t st = sbase + (uint32_t)(s * QSTAGE_E * 2);
#pragma unroll
        for (int t = 0; t < 2; ++t) {
#pragma unroll
            for (int g2 = 0; g2 < 2; ++g2) {
                const int g = tid + g2 * 256;
                const int row = g >> 2, part = g & 3;
                const uint32_t dst = st + (uint32_t)(t * TILE_E + row * SROW + part * 8) * 2;
                const __half* src = srcs[t] + (size_t)(rowoff[t] + row) * K + k0 + part * 8;
                cp16(dst, src);
            }
        }
    };

    const int KCH = K / BK;
    load_stage(0, 0);
    CP_COMMIT();

    for (int c = 0; c < KCH; ++c) {
        if (c + 1 < KCH) { load_stage((c + 1) & 1, (c + 1) * BK); CP_COMMIT(); CP_WAIT(1); }
        else             { CP_WAIT(0); }
        __syncthreads();

        const __half* stg = smemh + (c & 1) * QSTAGE_E;
        const __half* Ah = stg;
        const __half* Bh = stg + TILE_E;

#pragma unroll
        for (int k0 = 0; k0 < BK; k0 += 16) {
            uint32_t ah[4][4], bh[4][2];
#pragma unroll
            for (int mi = 0; mi < 4; ++mi) {
                const int base = (wm * 64 + mi * 16 + tr) * SROW + k0 + tc2;
                ah[mi][0] = *(const uint32_t*)(Ah + base);
                ah[mi][1] = *(const uint32_t*)(Ah + base + 8 * SROW);
                ah[mi][2] = *(const uint32_t*)(Ah + base + 8);
                ah[mi][3] = *(const uint32_t*)(Ah + base + 8 * SROW + 8);
            }
#pragma unroll
            for (int ni = 0; ni < 4; ++ni) {
                const int base = (wn * 32 + ni * 8 + tr) * SROW + k0 + tc2;
                bh[ni][0] = *(const uint32_t*)(Bh + base);
                bh[ni][1] = *(const uint32_t*)(Bh + base + 8);
            }
#pragma unroll
            for (int mi = 0; mi < 4; ++mi)
#pragma unroll
                for (int ni = 0; ni < 4; ++ni)
                    mma_f16(acc[mi][ni], ah[mi][0], ah[mi][1], ah[mi][2], ah[mi][3],
                            bh[ni][0], bh[ni][1]);
        }
        __syncthreads();
    }

    // ---- epilogue: plain fp16 Q/K per-head + transposed V ----
    if (bn < 2 * D_MODEL) {
        __half* H = (bn < D_MODEL) ? q_o : k_o;
        const int roff = (bn < D_MODEL) ? bn : bn - D_MODEL;
#pragma unroll
        for (int mi = 0; mi < 4; ++mi) {
            const int r = bm + wm * 64 + mi * 16 + tr;
            const int b = r >> 11, row = r & 2047;
#pragma unroll
            for (int ni = 0; ni < 4; ++ni) {
                const int cl = wn * 32 + ni * 8 + tc2;
                const float b0 = bias[bn + cl], b1 = bias[bn + cl + 1];
                const int cg = roff + cl, hh = cg >> 6, e = cg & 63;
                const size_t base =
                    (((size_t)b * NHEADS + hh) * SEQ + row) * HDIM + e;
                __half2 u01(__float2half(acc[mi][ni][0] + b0),
                            __float2half(acc[mi][ni][1] + b1));
                __half2 u23(__float2half(acc[mi][ni][2] + b0),
                            __float2half(acc[mi][ni][3] + b1));
                *(__half2*)(H + base)            = u01;
                *(__half2*)(H + base + 8 * HDIM) = u23;
            }
        }
    } else {
        float* sf = (float*)smemh;
#pragma unroll
        for (int mi = 0; mi < 4; ++mi) {
            const int r0 = wm * 64 + mi * 16 + tr;
#pragma unroll
            for (int ni = 0; ni < 4; ++ni) {
                const int cl = wn * 32 + ni * 8 + tc2;
                const float b0 = bias[bn + cl], b1 = bias[bn + cl + 1];
                sf[r0 * 129 + cl]           = acc[mi][ni][0] + b0;
                sf[r0 * 129 + cl + 1]       = acc[mi][ni][1] + b1;
                sf[(r0 + 8) * 129 + cl]     = acc[mi][ni][2] + b0;
                sf[(r0 + 8) * 129 + cl + 1] = acc[mi][ni][3] + b1;
            }
        }
        __syncthreads();
        for (int idx = tid; idx < 128 * 64; idx += 256) {
            const int el = idx >> 6, rp = idx & 63;
            const float f0 = sf[(2 * rp) * 129 + el];
            const float f1 = sf[(2 * rp + 1) * 129 + el];
            const int cg = bn - 2 * D_MODEL + el, hh = cg >> 6, e = cg & 63;
            const int rg = bm + 2 * rp, b = rg >> 11, row = rg & 2047;
            const size_t base = (((size_t)b * NHEADS + hh) * HDIM + e) * SEQ + row;
            *(__half2*)(vt_o + base) = __half2(__float2half(f0), __float2half(f1));
        }
    }
}

// ---- swa: fp16 1-term S, P hi/lo 2-term PV; pure cp.async fill ---------------
#define SROW2 72
#define QT (64 * SROW2)
#define SWA_SMEM (5 * QT * 2)           /* Q + 2 stages x (K, Vt) */

__global__ __launch_bounds__(128, 2)
void swa_tensor(const __half* __restrict__ q_g, const __half* __restrict__ k_g,
                const __half* __restrict__ vt_g,
                __half* __restrict__ ahi, __half* __restrict__ alo)
{
    extern __shared__ __half smf[];
    const int tid = threadIdx.x, lane = tid & 31, w = tid >> 5;
    const int bh = blockIdx.y;
    const int q0 = blockIdx.x * 64;
    const int tr = lane >> 2, tc2 = (lane & 3) * 2;

    const uint32_t sQ = smem_u32(smf);

    const size_t qkbase = (size_t)bh * SEQ * HDIM;
    const size_t vbase  = (size_t)bh * HDIM * SEQ;

    auto load_qk = [&](uint32_t sdst, const __half* src) {
#pragma unroll
        for (int it = 0; it < 4; ++it) {
            const int g = it * 128 + tid;
            const int row = g >> 3, ch = g & 7;
            cp16(sdst + (uint32_t)(row * SROW2 + ch * 8) * 2,
                 src + (size_t)row * HDIM + ch * 8);
        }
    };
    auto load_vt = [&](uint32_t sdst, const __half* src) {
#pragma unroll
        for (int it = 0; it < 4; ++it) {
            const int g = it * 128 + tid;
            const int row = g >> 3, ch = g & 7;
            cp16(sdst + (uint32_t)(row * SROW2 + ch * 8) * 2,
                 src + (size_t)row * SEQ + ch * 8);
        }
    };
    auto issue_stage = [&](int s, int j0) {
        const uint32_t st = sQ + (uint32_t)((1 + 2 * s) * QT) * 2;
        load_qk(st,          k_g + qkbase + (size_t)j0 * HDIM);
        load_vt(st + QT * 2, vt_g + vbase + j0);
    };

    const int kt0 = max(0, (int)blockIdx.x - 4);
    const int kt1 = blockIdx.x;

    load_qk(sQ, q_g + qkbase + (size_t)q0 * HDIM);
    issue_stage(0, kt0 * 64);
    CP_COMMIT();

    uint32_t qf[4][4];
    float o[8][4];
#pragma unroll
    for (int ni = 0; ni < 8; ++ni)
#pragma unroll
        for (int j = 0; j < 4; ++j) o[ni][j] = 0.f;
    float m0 = -1e30f, m1 = -1e30f, l0 = 0.f, l1 = 0.f;
    const int i0 = q0 + w * 16 + tr;
    const int i1 = i0 + 8;

    for (int kt = kt0; kt <= kt1; ++kt) {
        const int s = (kt - kt0) & 1;
        if (kt + 1 <= kt1) { issue_stage(s ^ 1, (kt + 1) * 64); CP_COMMIT(); CP_WAIT(1); }
        else               { CP_WAIT(0); }
        __syncthreads();

        if (kt == kt0) {
            const __half* Q = smf;
#pragma unroll
            for (int ks = 0; ks < 4; ++ks) {
                const int base = (w * 16 + tr) * SROW2 + ks * 16 + tc2;
                qf[ks][0] = *(const uint32_t*)(Q + base);
                qf[ks][1] = *(const uint32_t*)(Q + base + 8 * SROW2);
                qf[ks][2] = *(const uint32_t*)(Q + base + 8);
                qf[ks][3] = *(const uint32_t*)(Q + base + 8 * SROW2 + 8);
            }
        }

        const __half* Kt = smf + (1 + 2 * s) * QT;
        const __half* Vt = Kt + QT;
        const int j0 = kt * 64;

        // ---- S = Q K^T (single fp16 pass, f32 acc) ----
        float sacc[8][4];
#pragma unroll
        for (int ni = 0; ni < 8; ++ni)
#pragma unroll
            for (int j = 0; j < 4; ++j) sacc[ni][j] = 0.f;
#pragma unroll
        for (int ks = 0; ks < 4; ++ks) {
            uint32_t kb[8][2];
#pragma unroll
            for (int ni = 0; ni < 8; ++ni) {
                const int base = (ni * 8 + tr) * SROW2 + ks * 16 + tc2;
                kb[ni][0] = *(const uint32_t*)(Kt + base);
                kb[ni][1] = *(const uint32_t*)(Kt + base + 8);
            }
#pragma unroll
            for (int ni = 0; ni < 8; ++ni)
                mma_f16(sacc[ni], qf[ks][0], qf[ks][1], qf[ks][2], qf[ks][3],
                        kb[ni][0], kb[ni][1]);
        }

        // ---- mask + online softmax ----
        float tmax0 = -1e30f, tmax1 = -1e30f;
#pragma unroll
        for (int ni = 0; ni < 8; ++ni) {
            const int ja = j0 + ni * 8 + tc2, jb = ja + 1;
            sacc[ni][0] = (ja <= i0 && (i0 - ja) < WINDOW) ? sacc[ni][0] * 0.125f : -1e30f;
            sacc[ni][1] = (jb <= i0 && (i0 - jb) < WINDOW) ? sacc[ni][1] * 0.125f : -1e30f;
            sacc[ni][2] = (ja <= i1 && (i1 - ja) < WINDOW) ? sacc[ni][2] * 0.125f : -1e30f;
            sacc[ni][3] = (jb <= i1 && (i1 - jb) < WINDOW) ? sacc[ni][3] * 0.125f : -1e30f;
            tmax0 = fmaxf(tmax0, fmaxf(sacc[ni][0], sacc[ni][1]));
            tmax1 = fmaxf(tmax1, fmaxf(sacc[ni][2], sacc[ni][3]));
        }
        tmax0 = fmaxf(tmax0, __shfl_xor_sync(0xffffffff, tmax0, 1));
        tmax0 = fmaxf(tmax0, __shfl_xor_sync(0xffffffff, tmax0, 2));
        tmax1 = fmaxf(tmax1, __shfl_xor_sync(0xffffffff, tmax1, 1));
        tmax1 = fmaxf(tmax1, __shfl_xor_sync(0xffffffff, tmax1, 2));

        const float mn0 = fmaxf(m0, tmax0), mn1 = fmaxf(m1, tmax1);
        const float sc0 = __expf(m0 - mn0), sc1 = __expf(m1 - mn1);
        m0 = mn0; m1 = mn1;

        float rs0 = 0.f, rs1 = 0.f;
        uint32_t ph[8][2], pl[8][2];
#pragma unroll
        for (int ni = 0; ni < 8; ++ni) {
            float p0 = __expf(sacc[ni][0] - mn0);
            float p1 = __expf(sacc[ni][1] - mn0);
            float p2 = __expf(sacc[ni][2] - mn1);
            float p3 = __expf(sacc[ni][3] - mn1);
            rs0 += p0 + p1; rs1 += p2 + p3;
            __half b0 = __float2half(p0), b1 = __float2half(p1);
            __half b2 = __float2half(p2), b3 = __float2half(p3);
            __half2 t01(b0, b1), t23(b2, b3);
            __half2 w01(__float2half(p0 - __half2float(b0)),
                        __float2half(p1 - __half2float(b1)));
            __half2 w23(__float2half(p2 - __half2float(b2)),
                        __float2half(p3 - __half2float(b3)));
            ph[ni][0] = *(uint32_t*)&t01;
            ph[ni][1] = *(uint32_t*)&t23;
            pl[ni][0] = *(uint32_t*)&w01;
            pl[ni][1] = *(uint32_t*)&w23;
        }
        rs0 += __shfl_xor_sync(0xffffffff, rs0, 1);
        rs0 += __shfl_xor_sync(0xffffffff, rs0, 2);
        rs1 += __shfl_xor_sync(0xffffffff, rs1, 1);
        rs1 += __shfl_xor_sync(0xffffffff, rs1, 2);
        l0 = l0 * sc0 + rs0;
        l1 = l1 * sc1 + rs1;

#pragma unroll
        for (int ni = 0; ni < 8; ++ni) {
            o[ni][0] *= sc0; o[ni][1] *= sc0;
            o[ni][2] *= sc1; o[ni][3] *= sc1;
        }

        // ---- O += P V (P hi/lo 2-pass, f32 acc) ----
#pragma unroll
        for (int ks = 0; ks < 4; ++ks) {
            uint32_t vb[8][2];
#pragma unroll
            for (int ni = 0; ni < 8; ++ni) {
                const int base = (ni * 8 + tr) * SROW2 + ks * 16 + tc2;
                vb[ni][0] = *(const uint32_t*)(Vt + base);
                vb[ni][1] = *(const uint32_t*)(Vt + base + 8);
            }
#pragma unroll
            for (int ni = 0; ni < 8; ++ni)
                mma_f16(o[ni], ph[2*ks][0], ph[2*ks][1], ph[2*ks+1][0], ph[2*ks+1][1],
                        vb[ni][0], vb[ni][1]);
#pragma unroll
            for (int ni = 0; ni < 8; ++ni)
                mma_f16(o[ni], pl[2*ks][0], pl[2*ks][1], pl[2*ks+1][0], pl[2*ks+1][1],
                        vb[ni][0], vb[ni][1]);
        }
        __syncthreads();
    }

    const int b = bh >> 4, h = bh & 15;
    const float inv0 = 1.f / l0, inv1 = 1.f / l1;
    const size_t t0 = (size_t)(b * SEQ + i0) * D_MODEL + (size_t)h * HDIM;
    const size_t t1 = (size_t)(b * SEQ + i1) * D_MODEL + (size_t)h * HDIM;
#pragma unroll
    for (int ni = 0; ni < 8; ++ni) {
        const int c = ni * 8 + tc2;
        float f0 = o[ni][0] * inv0, f1 = o[ni][1] * inv0;
        float f2 = o[ni][2] * inv1, f3 = o[ni][3] * inv1;
        __half h0 = __float2half(f0), h1 = __float2half(f1);
        __half h2 = __float2half(f2), h3 = __float2half(f3);
        __half2 u01(h0, h1), u23(h2, h3);
        __half2 l01(__float2half(f0 - __half2float(h0)), __float2half(f1 - __half2float(h1)));
        __half2 l23(__float2half(f2 - __half2float(h2)), __float2half(f3 - __half2float(h3)));
        *(__half2*)(ahi + t0 + c) = u01;
        *(__half2*)(ahi + t1 + c) = u23;
        *(__half2*)(alo + t0 + c) = l01;
        *(__half2*)(alo + t1 + c) = l23;
    }
}

// ---- proj GEMM: fp16 2-term (unchanged) --------------------------------------
#define PTILE_E (128 * SROW)
#define PSTAGE_E (3 * PTILE_E)
#define PSMEM_SZ (2 * PSTAGE_E * 2)

__global__ __launch_bounds__(256, 2)
void gemm_proj(const __half* __restrict__ Ahi, const __half* __restrict__ Alo,
               const __half* __restrict__ Bh_g,
               const float* __restrict__ bias, float* __restrict__ C,
               int M, int N, int K)
{
    extern __shared__ __half smemh[];
    const int tid  = threadIdx.x;
    const int lane = tid & 31;
    const int wid  = tid >> 5;
    const int wm   = wid >> 2;
    const int wn   = wid & 3;
    const int tr   = lane >> 2;
    const int tc2  = (lane & 3) * 2;
    const int bm   = blockIdx.y * BM;
    const int bn   = blockIdx.x * BN;

    const uint32_t sbase = smem_u32(smemh);

    float acc[4][4][4];
#pragma unroll
    for (int i = 0; i < 4; ++i)
#pragma unroll
        for (int j = 0; j < 4; ++j)
#pragma unroll
            for (int r = 0; r < 4; ++r) acc[i][j][r] = 0.f;

    const __half* srcs[3] = { Ahi, Alo, Bh_g };
    const int rowoff[3] = { bm, bm, bn };

    auto load_stage = [&](int s, int k0) {
        const uint32_t st = sbase + (uint32_t)(s * PSTAGE_E * 2);
#pragma unroll
        for (int t = 0; t < 3; ++t) {
#pragma unroll
            for (int g2 = 0; g2 < 2; ++g2) {
                const int g = tid + g2 * 256;
                const int row = g >> 2, part = g & 3;
                const uint32_t dst = st + (uint32_t)(t * PTILE_E + row * SROW + part * 8) * 2;
                const __half* src = srcs[t] + (size_t)(rowoff[t] + row) * K + k0 + part * 8;
                cp16(dst, src);
            }
        }
    };

    const int KCH = K / BK;
    load_stage(0, 0);
    CP_COMMIT();

    for (int c = 0; c < KCH; ++c) {
        if (c + 1 < KCH) { load_stage((c + 1) & 1, (c + 1) * BK); CP_COMMIT(); CP_WAIT(1); }
        else             { CP_WAIT(0); }
        __syncthreads();

        const __half* stg = smemh + (c & 1) * PSTAGE_E;
        const __half* Ah = stg;
        const __half* Al = stg + PTILE_E;
        const __half* Bh = stg + 2 * PTILE_E;

#pragma unroll
        for (int k0 = 0; k0 < BK; k0 += 16) {
            uint32_t ah[4][4], al[4][4], bh[4][2];
#pragma unroll
            for (int mi = 0; mi < 4; ++mi) {
                const int base = (wm * 64 + mi * 16 + tr) * SROW + k0 + tc2;
                ah[mi][0] = *(const uint32_t*)(Ah + base);
                ah[mi][1] = *(const uint32_t*)(Ah + base + 8 * SROW);
                ah[mi][2] = *(const uint32_t*)(Ah + base + 8);
                ah[mi][3] = *(const uint32_t*)(Ah + base + 8 * SROW + 8);
                al[mi][0] = *(const uint32_t*)(Al + base);
                al[mi][1] = *(const uint32_t*)(Al + base + 8 * SROW);
                al[mi][2] = *(const uint32_t*)(Al + base + 8);
                al[mi][3] = *(const uint32_t*)(Al + base + 8 * SROW + 8);
            }
#pragma unroll
            for (int ni = 0; ni < 4; ++ni) {
                const int base = (wn * 32 + ni * 8 + tr) * SROW + k0 + tc2;
                bh[ni][0] = *(const uint32_t*)(Bh + base);
                bh[ni][1] = *(const uint32_t*)(Bh + base + 8);
            }
#pragma unroll
            for (int mi = 0; mi < 4; ++mi)
#pragma unroll
                for (int ni = 0; ni < 4; ++ni)
                    mma_f16(acc[mi][ni], ah[mi][0], ah[mi][1], ah[mi][2], ah[mi][3],
                            bh[ni][0], bh[ni][1]);
#pragma unroll
            for (int mi = 0; mi < 4; ++mi)
#pragma unroll
                for (int ni = 0; ni < 4; ++ni)
                    mma_f16(acc[mi][ni], al[mi][0], al[mi][1], al[mi][2], al[mi][3],
                            bh[ni][0], bh[ni][1]);
        }
        __syncthreads();
    }

#pragma unroll
    for (int mi = 0; mi < 4; ++mi) {
        const int r = bm + wm * 64 + mi * 16 + tr;
#pragma unroll
        for (int ni = 0; ni < 4; ++ni) {
            const int cidx = bn + wn * 32 + ni * 8 + tc2;
            const float b0 = bias[cidx], b1 = bias[cidx + 1];
            float2 v0 = make_float2(acc[mi][ni][0] + b0, acc[mi][ni][1] + b1);
            float2 v1 = make_float2(acc[mi][ni][2] + b0, acc[mi][ni][3] + b1);
            *(float2*)(C + (size_t)r * N + cidx)       = v0;
            *(float2*)(C + (size_t)(r + 8) * N + cidx) = v1;
        }
    }
}

// ---------------------------------------------------------------------------
extern "C" void kernel_launch(void* const* d_in, const int* in_sizes, int n_in,
                              void* d_out, int out_size)
{
    const float* x      = (const float*)d_in[0];
    const float* w_qkv  = (const float*)d_in[1];
    const float* b_qkv  = (const float*)d_in[2];
    const float* w_proj = (const float*)d_in[3];
    const float* b_proj = (const float*)d_in[4];
    float* out = (float*)d_out;

    __half *xf, *wq, *wph, *ahi, *alo, *q, *k, *vt;
    cudaGetSymbolAddress((void**)&xf, g_xf);
    cudaGetSymbolAddress((void**)&wq, g_wq);
    cudaGetSymbolAddress((void**)&wph, g_wph);
    cudaGetSymbolAddress((void**)&q, g_q);
    cudaGetSymbolAddress((void**)&k, g_k);
    cudaGetSymbolAddress((void**)&vt, g_vt);
    cudaGetSymbolAddress((void**)&ahi, g_ahi);
    cudaGetSymbolAddress((void**)&alo, g_alo);

    cudaFuncSetAttribute(gemm_qkv,
                         cudaFuncAttributeMaxDynamicSharedMemorySize, QSMEM_SZ);
    cudaFuncSetAttribute(swa_tensor,
                         cudaFuncAttributeMaxDynamicSharedMemorySize, SWA_SMEM);
    cudaFuncSetAttribute(gemm_proj,
                         cudaFuncAttributeMaxDynamicSharedMemorySize, PSMEM_SZ);

    {
        int n4x = MTOT * D_MODEL / 4;
        int n4q = QKV_LD * D_MODEL / 4;
        int n4p = D_MODEL * D_MODEL / 4;
        cvt_half<<<n4x / 256, 256>>>((const float4*)x, xf, n4x);
        cvt_half<<<n4q / 256, 256>>>((const float4*)w_qkv, wq, n4q);
        cvt_half<<<n4p / 256, 256>>>((const float4*)w_proj, wph, n4p);
    }

    // 1) QKV projection (fp16 1-term) -> per-head fp16 Q,K + transposed V
    gemm_qkv<<<dim3(QKV_LD / BN, MTOT / BM), 256, QSMEM_SZ>>>(
        xf, wq, b_qkv, q, k, vt);

    // 2) sliding-window attention (fp16 S 1-pass, PV 2-pass) -> fp16 hi/lo
    swa_tensor<<<dim3(SEQ / 64, BHTOT), 128, SWA_SMEM>>>(
        q, k, vt, ahi, alo);

    // 3) output projection (fp16 2-term)
    gemm_proj<<<dim3(D_MODEL / BN, MTOT / BM), 256, PSMEM_SZ>>>(
        ahi, alo, wph, b_proj, out, MTOT, D_MODEL, D_MODEL);
}

// round 15
// speedup vs baseline: 1.8824x; 1.1746x over previous
#include <cuda_runtime.h>
#include <cuda_fp16.h>
#include <cstdint>

#define D_MODEL 1024
#define NHEADS  16
#define HDIM    64
#define WINDOW  256
#define BATCH   2
#define SEQ     2048
#define MTOT    (BATCH * SEQ)          /* 4096 */
#define QKV_LD  (3 * D_MODEL)          /* 3072 */
#define BHTOT   (BATCH * NHEADS)       /* 32 */

// ---- scratch --------------------------------------------------------------
__device__ __half g_xf[(size_t)MTOT * D_MODEL];
__device__ __half g_wq[(size_t)QKV_LD * D_MODEL];
__device__ __half g_wph[(size_t)D_MODEL * D_MODEL];
// per-head Q/K: [bh][token][e]; V transposed: [bh][e][token]  (plain fp16)
__device__ __half g_q[(size_t)BHTOT * SEQ * HDIM];
__device__ __half g_k[(size_t)BHTOT * SEQ * HDIM];
__device__ __half g_vt[(size_t)BHTOT * HDIM * SEQ];
// attention out (plain fp16) for proj
__device__ __half g_af[(size_t)MTOT * D_MODEL];

// ---- PTX helpers ------------------------------------------------------------
__device__ __forceinline__ uint32_t smem_u32(const void* p) {
    uint32_t a;
    asm("{ .reg .u64 t; cvta.to.shared.u64 t, %1; cvt.u32.u64 %0, t; }" : "=r"(a) : "l"(p));
    return a;
}
__device__ __forceinline__ void cp16(uint32_t dst, const void* src) {
    asm volatile("cp.async.cg.shared.global [%0], [%1], 16;" :: "r"(dst), "l"(src));
}
#define CP_COMMIT()  asm volatile("cp.async.commit_group;" ::: "memory")
#define CP_WAIT(n)   asm volatile("cp.async.wait_group %0;" :: "n"(n) : "memory")

__device__ __forceinline__ void mma_f16(float* d, uint32_t a0, uint32_t a1,
                                        uint32_t a2, uint32_t a3,
                                        uint32_t b0, uint32_t b1) {
    asm("mma.sync.aligned.m16n8k16.row.col.f32.f16.f16.f32 "
        "{%0,%1,%2,%3}, {%4,%5,%6,%7}, {%8,%9}, {%0,%1,%2,%3};"
        : "+f"(d[0]), "+f"(d[1]), "+f"(d[2]), "+f"(d[3])
        : "r"(a0), "r"(a1), "r"(a2), "r"(a3), "r"(b0), "r"(b1));
}

// ---- fused fp32 -> fp16 convert for x, w_qkv, w_proj --------------------------
#define N4X (MTOT * D_MODEL / 4)       /* 1048576 */
#define N4Q (QKV_LD * D_MODEL / 4)     /* 786432 */
#define N4P (D_MODEL * D_MODEL / 4)    /* 262144 */

__global__ __launch_bounds__(256)
void cvt_all(const float4* __restrict__ x, const float4* __restrict__ wq,
             const float4* __restrict__ wp,
             __half* __restrict__ xo, __half* __restrict__ wqo,
             __half* __restrict__ wpo)
{
    int i = blockIdx.x * 256 + threadIdx.x;
    const float4* src;
    __half* dst;
    int idx;
    if (i < N4X)            { src = x;  dst = xo;  idx = i; }
    else if (i < N4X + N4Q) { src = wq; dst = wqo; idx = i - N4X; }
    else                    { src = wp; dst = wpo; idx = i - N4X - N4Q; }
    float4 v = src[idx];
    __half2* op = (__half2*)(dst + (size_t)idx * 4);
    op[0] = __half2(__float2half(v.x), __float2half(v.y));
    op[1] = __half2(__float2half(v.z), __float2half(v.w));
}

// ---- QKV GEMM: fp16 1-term; epilogue writes fp16 Q/K + transposed V ----------
#define BM 128
#define BN 128
#define BK 32
#define SROW 40
#define TILE_E (128 * SROW)
#define GSTAGE_E (2 * TILE_E)
#define GSMEM_SZ 66048                  /* epilogue V stage needs 128*129*4 */

__global__ __launch_bounds__(256, 2)
void gemm_qkv(const __half* __restrict__ A, const __half* __restrict__ W,
              const float* __restrict__ bias,
              __half* __restrict__ q_o, __half* __restrict__ k_o,
              __half* __restrict__ vt_o)
{
    extern __shared__ __half smemh[];
    const int K = D_MODEL;
    const int tid  = threadIdx.x;
    const int lane = tid & 31;
    const int wid  = tid >> 5;
    const int wm   = wid >> 2;
    const int wn   = wid & 3;
    const int tr   = lane >> 2;
    const int tc2  = (lane & 3) * 2;
    const int bm   = blockIdx.y * BM;
    const int bn   = blockIdx.x * BN;

    const uint32_t sbase = smem_u32(smemh);

    float acc[4][4][4];
#pragma unroll
    for (int i = 0; i < 4; ++i)
#pragma unroll
        for (int j = 0; j < 4; ++j)
#pragma unroll
            for (int r = 0; r < 4; ++r) acc[i][j][r] = 0.f;

    const __half* srcs[2] = { A, W };
    const int rowoff[2] = { bm, bn };

    auto load_stage = [&](int s, int k0) {
        const uint32_t st = sbase + (uint32_t)(s * GSTAGE_E * 2);
#pragma unroll
        for (int t = 0; t < 2; ++t) {
#pragma unroll
            for (int g2 = 0; g2 < 2; ++g2) {
                const int g = tid + g2 * 256;
                const int row = g >> 2, part = g & 3;
                const uint32_t dst = st + (uint32_t)(t * TILE_E + row * SROW + part * 8) * 2;
                const __half* src = srcs[t] + (size_t)(rowoff[t] + row) * K + k0 + part * 8;
                cp16(dst, src);
            }
        }
    };

    const int KCH = K / BK;
    load_stage(0, 0);
    CP_COMMIT();

    for (int c = 0; c < KCH; ++c) {
        if (c + 1 < KCH) { load_stage((c + 1) & 1, (c + 1) * BK); CP_COMMIT(); CP_WAIT(1); }
        else             { CP_WAIT(0); }
        __syncthreads();

        const __half* stg = smemh + (c & 1) * GSTAGE_E;
        const __half* Ah = stg;
        const __half* Bh = stg + TILE_E;

#pragma unroll
        for (int k0 = 0; k0 < BK; k0 += 16) {
            uint32_t ah[4][4], bh[4][2];
#pragma unroll
            for (int mi = 0; mi < 4; ++mi) {
                const int base = (wm * 64 + mi * 16 + tr) * SROW + k0 + tc2;
                ah[mi][0] = *(const uint32_t*)(Ah + base);
                ah[mi][1] = *(const uint32_t*)(Ah + base + 8 * SROW);
                ah[mi][2] = *(const uint32_t*)(Ah + base + 8);
                ah[mi][3] = *(const uint32_t*)(Ah + base + 8 * SROW + 8);
            }
#pragma unroll
            for (int ni = 0; ni < 4; ++ni) {
                const int base = (wn * 32 + ni * 8 + tr) * SROW + k0 + tc2;
                bh[ni][0] = *(const uint32_t*)(Bh + base);
                bh[ni][1] = *(const uint32_t*)(Bh + base + 8);
            }
#pragma unroll
            for (int mi = 0; mi < 4; ++mi)
#pragma unroll
                for (int ni = 0; ni < 4; ++ni)
                    mma_f16(acc[mi][ni], ah[mi][0], ah[mi][1], ah[mi][2], ah[mi][3],
                            bh[ni][0], bh[ni][1]);
        }
        __syncthreads();
    }

    // ---- epilogue: plain fp16 Q/K per-head + transposed V ----
    if (bn < 2 * D_MODEL) {
        __half* H = (bn < D_MODEL) ? q_o : k_o;
        const int roff = (bn < D_MODEL) ? bn : bn - D_MODEL;
#pragma unroll
        for (int mi = 0; mi < 4; ++mi) {
            const int r = bm + wm * 64 + mi * 16 + tr;
            const int b = r >> 11, row = r & 2047;
#pragma unroll
            for (int ni = 0; ni < 4; ++ni) {
                const int cl = wn * 32 + ni * 8 + tc2;
                const float b0 = bias[bn + cl], b1 = bias[bn + cl + 1];
                const int cg = roff + cl, hh = cg >> 6, e = cg & 63;
                const size_t base =
                    (((size_t)b * NHEADS + hh) * SEQ + row) * HDIM + e;
                __half2 u01(__float2half(acc[mi][ni][0] + b0),
                            __float2half(acc[mi][ni][1] + b1));
                __half2 u23(__float2half(acc[mi][ni][2] + b0),
                            __float2half(acc[mi][ni][3] + b1));
                *(__half2*)(H + base)            = u01;
                *(__half2*)(H + base + 8 * HDIM) = u23;
            }
        }
    } else {
        float* sf = (float*)smemh;
#pragma unroll
        for (int mi = 0; mi < 4; ++mi) {
            const int r0 = wm * 64 + mi * 16 + tr;
#pragma unroll
            for (int ni = 0; ni < 4; ++ni) {
                const int cl = wn * 32 + ni * 8 + tc2;
                const float b0 = bias[bn + cl], b1 = bias[bn + cl + 1];
                sf[r0 * 129 + cl]           = acc[mi][ni][0] + b0;
                sf[r0 * 129 + cl + 1]       = acc[mi][ni][1] + b1;
                sf[(r0 + 8) * 129 + cl]     = acc[mi][ni][2] + b0;
                sf[(r0 + 8) * 129 + cl + 1] = acc[mi][ni][3] + b1;
            }
        }
        __syncthreads();
        for (int idx = tid; idx < 128 * 64; idx += 256) {
            const int el = idx >> 6, rp = idx & 63;
            const float f0 = sf[(2 * rp) * 129 + el];
            const float f1 = sf[(2 * rp + 1) * 129 + el];
            const int cg = bn - 2 * D_MODEL + el, hh = cg >> 6, e = cg & 63;
            const int rg = bm + 2 * rp, b = rg >> 11, row = rg & 2047;
            const size_t base = (((size_t)b * NHEADS + hh) * HDIM + e) * SEQ + row;
            *(__half2*)(vt_o + base) = __half2(__float2half(f0), __float2half(f1));
        }
    }
}

// ---- swa: fp16 1-term S, P hi/lo 2-term PV; epilogue plain fp16 --------------
#define SROW2 72
#define QT (64 * SROW2)
#define SWA_SMEM (5 * QT * 2)           /* Q + 2 stages x (K, Vt) */

__global__ __launch_bounds__(128, 2)
void swa_tensor(const __half* __restrict__ q_g, const __half* __restrict__ k_g,
                const __half* __restrict__ vt_g, __half* __restrict__ af)
{
    extern __shared__ __half smf[];
    const int tid = threadIdx.x, lane = tid & 31, w = tid >> 5;
    const int bh = blockIdx.y;
    const int q0 = blockIdx.x * 64;
    const int tr = lane >> 2, tc2 = (lane & 3) * 2;

    const uint32_t sQ = smem_u32(smf);

    const size_t qkbase = (size_t)bh * SEQ * HDIM;
    const size_t vbase  = (size_t)bh * HDIM * SEQ;

    auto load_qk = [&](uint32_t sdst, const __half* src) {
#pragma unroll
        for (int it = 0; it < 4; ++it) {
            const int g = it * 128 + tid;
            const int row = g >> 3, ch = g & 7;
            cp16(sdst + (uint32_t)(row * SROW2 + ch * 8) * 2,
                 src + (size_t)row * HDIM + ch * 8);
        }
    };
    auto load_vt = [&](uint32_t sdst, const __half* src) {
#pragma unroll
        for (int it = 0; it < 4; ++it) {
            const int g = it * 128 + tid;
            const int row = g >> 3, ch = g & 7;
            cp16(sdst + (uint32_t)(row * SROW2 + ch * 8) * 2,
                 src + (size_t)row * SEQ + ch * 8);
        }
    };
    auto issue_stage = [&](int s, int j0) {
        const uint32_t st = sQ + (uint32_t)((1 + 2 * s) * QT) * 2;
        load_qk(st,          k_g + qkbase + (size_t)j0 * HDIM);
        load_vt(st + QT * 2, vt_g + vbase + j0);
    };

    const int kt0 = max(0, (int)blockIdx.x - 4);
    const int kt1 = blockIdx.x;

    load_qk(sQ, q_g + qkbase + (size_t)q0 * HDIM);
    issue_stage(0, kt0 * 64);
    CP_COMMIT();

    uint32_t qf[4][4];
    float o[8][4];
#pragma unroll
    for (int ni = 0; ni < 8; ++ni)
#pragma unroll
        for (int j = 0; j < 4; ++j) o[ni][j] = 0.f;
    float m0 = -1e30f, m1 = -1e30f, l0 = 0.f, l1 = 0.f;
    const int i0 = q0 + w * 16 + tr;
    const int i1 = i0 + 8;

    for (int kt = kt0; kt <= kt1; ++kt) {
        const int s = (kt - kt0) & 1;
        if (kt + 1 <= kt1) { issue_stage(s ^ 1, (kt + 1) * 64); CP_COMMIT(); CP_WAIT(1); }
        else               { CP_WAIT(0); }
        __syncthreads();

        if (kt == kt0) {
            const __half* Q = smf;
#pragma unroll
            for (int ks = 0; ks < 4; ++ks) {
                const int base = (w * 16 + tr) * SROW2 + ks * 16 + tc2;
                qf[ks][0] = *(const uint32_t*)(Q + base);
                qf[ks][1] = *(const uint32_t*)(Q + base + 8 * SROW2);
                qf[ks][2] = *(const uint32_t*)(Q + base + 8);
                qf[ks][3] = *(const uint32_t*)(Q + base + 8 * SROW2 + 8);
            }
        }

        const __half* Kt = smf + (1 + 2 * s) * QT;
        const __half* Vt = Kt + QT;
        const int j0 = kt * 64;

        // ---- S = Q K^T (single fp16 pass, f32 acc) ----
        float sacc[8][4];
#pragma unroll
        for (int ni = 0; ni < 8; ++ni)
#pragma unroll
            for (int j = 0; j < 4; ++j) sacc[ni][j] = 0.f;
#pragma unroll
        for (int ks = 0; ks < 4; ++ks) {
            uint32_t kb[8][2];
#pragma unroll
            for (int ni = 0; ni < 8; ++ni) {
                const int base = (ni * 8 + tr) * SROW2 + ks * 16 + tc2;
                kb[ni][0] = *(const uint32_t*)(Kt + base);
                kb[ni][1] = *(const uint32_t*)(Kt + base + 8);
            }
#pragma unroll
            for (int ni = 0; ni < 8; ++ni)
                mma_f16(sacc[ni], qf[ks][0], qf[ks][1], qf[ks][2], qf[ks][3],
                        kb[ni][0], kb[ni][1]);
        }

        // ---- mask + online softmax ----
        float tmax0 = -1e30f, tmax1 = -1e30f;
#pragma unroll
        for (int ni = 0; ni < 8; ++ni) {
            const int ja = j0 + ni * 8 + tc2, jb = ja + 1;
            sacc[ni][0] = (ja <= i0 && (i0 - ja) < WINDOW) ? sacc[ni][0] * 0.125f : -1e30f;
            sacc[ni][1] = (jb <= i0 && (i0 - jb) < WINDOW) ? sacc[ni][1] * 0.125f : -1e30f;
            sacc[ni][2] = (ja <= i1 && (i1 - ja) < WINDOW) ? sacc[ni][2] * 0.125f : -1e30f;
            sacc[ni][3] = (jb <= i1 && (i1 - jb) < WINDOW) ? sacc[ni][3] * 0.125f : -1e30f;
            tmax0 = fmaxf(tmax0, fmaxf(sacc[ni][0], sacc[ni][1]));
            tmax1 = fmaxf(tmax1, fmaxf(sacc[ni][2], sacc[ni][3]));
        }
        tmax0 = fmaxf(tmax0, __shfl_xor_sync(0xffffffff, tmax0, 1));
        tmax0 = fmaxf(tmax0, __shfl_xor_sync(0xffffffff, tmax0, 2));
        tmax1 = fmaxf(tmax1, __shfl_xor_sync(0xffffffff, tmax1, 1));
        tmax1 = fmaxf(tmax1, __shfl_xor_sync(0xffffffff, tmax1, 2));

        const float mn0 = fmaxf(m0, tmax0), mn1 = fmaxf(m1, tmax1);
        const float sc0 = __expf(m0 - mn0), sc1 = __expf(m1 - mn1);
        m0 = mn0; m1 = mn1;

        float rs0 = 0.f, rs1 = 0.f;
        uint32_t ph[8][2], pl[8][2];
#pragma unroll
        for (int ni = 0; ni < 8; ++ni) {
            float p0 = __expf(sacc[ni][0] - mn0);
            float p1 = __expf(sacc[ni][1] - mn0);
            float p2 = __expf(sacc[ni][2] - mn1);
            float p3 = __expf(sacc[ni][3] - mn1);
            rs0 += p0 + p1; rs1 += p2 + p3;
            __half b0 = __float2half(p0), b1 = __float2half(p1);
            __half b2 = __float2half(p2), b3 = __float2half(p3);
            __half2 t01(b0, b1), t23(b2, b3);
            __half2 w01(__float2half(p0 - __half2float(b0)),
                        __float2half(p1 - __half2float(b1)));
            __half2 w23(__float2half(p2 - __half2float(b2)),
                        __float2half(p3 - __half2float(b3)));
            ph[ni][0] = *(uint32_t*)&t01;
            ph[ni][1] = *(uint32_t*)&t23;
            pl[ni][0] = *(uint32_t*)&w01;
            pl[ni][1] = *(uint32_t*)&w23;
        }
        rs0 += __shfl_xor_sync(0xffffffff, rs0, 1);
        rs0 += __shfl_xor_sync(0xffffffff, rs0, 2);
        rs1 += __shfl_xor_sync(0xffffffff, rs1, 1);
        rs1 += __shfl_xor_sync(0xffffffff, rs1, 2);
        l0 = l0 * sc0 + rs0;
        l1 = l1 * sc1 + rs1;

#pragma unroll
        for (int ni = 0; ni < 8; ++ni) {
            o[ni][0] *= sc0; o[ni][1] *= sc0;
            o[ni][2] *= sc1; o[ni][3] *= sc1;
        }

        // ---- O += P V (P hi/lo 2-pass, f32 acc) ----
#pragma unroll
        for (int ks = 0; ks < 4; ++ks) {
            uint32_t vb[8][2];
#pragma unroll
            for (int ni = 0; ni < 8; ++ni) {
                const int base = (ni * 8 + tr) * SROW2 + ks * 16 + tc2;
                vb[ni][0] = *(const uint32_t*)(Vt + base);
                vb[ni][1] = *(const uint32_t*)(Vt + base + 8);
            }
#pragma unroll
            for (int ni = 0; ni < 8; ++ni)
                mma_f16(o[ni], ph[2*ks][0], ph[2*ks][1], ph[2*ks+1][0], ph[2*ks+1][1],
                        vb[ni][0], vb[ni][1]);
#pragma unroll
            for (int ni = 0; ni < 8; ++ni)
                mma_f16(o[ni], pl[2*ks][0], pl[2*ks][1], pl[2*ks+1][0], pl[2*ks+1][1],
                        vb[ni][0], vb[ni][1]);
        }
        __syncthreads();
    }

    const int b = bh >> 4, h = bh & 15;
    const float inv0 = 1.f / l0, inv1 = 1.f / l1;
    const size_t t0 = (size_t)(b * SEQ + i0) * D_MODEL + (size_t)h * HDIM;
    const size_t t1 = (size_t)(b * SEQ + i1) * D_MODEL + (size_t)h * HDIM;
#pragma unroll
    for (int ni = 0; ni < 8; ++ni) {
        const int c = ni * 8 + tc2;
        *(__half2*)(af + t0 + c) = __half2(__float2half(o[ni][0] * inv0),
                                           __float2half(o[ni][1] * inv0));
        *(__half2*)(af + t1 + c) = __half2(__float2half(o[ni][2] * inv1),
                                           __float2half(o[ni][3] * inv1));
    }
}

// ---- proj GEMM: fp16 1-term ---------------------------------------------------
__global__ __launch_bounds__(256, 2)
void gemm_proj(const __half* __restrict__ A, const __half* __restrict__ W,
               const float* __restrict__ bias, float* __restrict__ C,
               int M, int N, int K)
{
    extern __shared__ __half smemh[];
    const int tid  = threadIdx.x;
    const int lane = tid & 31;
    const int wid  = tid >> 5;
    const int wm   = wid >> 2;
    const int wn   = wid & 3;
    const int tr   = lane >> 2;
    const int tc2  = (lane & 3) * 2;
    const int bm   = blockIdx.y * BM;
    const int bn   = blockIdx.x * BN;

    const uint32_t sbase = smem_u32(smemh);

    float acc[4][4][4];
#pragma unroll
    for (int i = 0; i < 4; ++i)
#pragma unroll
        for (int j = 0; j < 4; ++j)
#pragma unroll
            for (int r = 0; r < 4; ++r) acc[i][j][r] = 0.f;

    const __half* srcs[2] = { A, W };
    const int rowoff[2] = { bm, bn };

    auto load_stage = [&](int s, int k0) {
        const uint32_t st = sbase + (uint32_t)(s * GSTAGE_E * 2);
#pragma unroll
        for (int t = 0; t < 2; ++t) {
#pragma unroll
            for (int g2 = 0; g2 < 2; ++g2) {
                const int g = tid + g2 * 256;
                const int row = g >> 2, part = g & 3;
                const uint32_t dst = st + (uint32_t)(t * TILE_E + row * SROW + part * 8) * 2;
                const __half* src = srcs[t] + (size_t)(rowoff[t] + row) * K + k0 + part * 8;
                cp16(dst, src);
            }
        }
    };

    const int KCH = K / BK;
    load_stage(0, 0);
    CP_COMMIT();

    for (int c = 0; c < KCH; ++c) {
        if (c + 1 < KCH) { load_stage((c + 1) & 1, (c + 1) * BK); CP_COMMIT(); CP_WAIT(1); }
        else             { CP_WAIT(0); }
        __syncthreads();

        const __half* stg = smemh + (c & 1) * GSTAGE_E;
        const __half* Ah = stg;
        const __half* Bh = stg + TILE_E;

#pragma unroll
        for (int k0 = 0; k0 < BK; k0 += 16) {
            uint32_t ah[4][4], bh[4][2];
#pragma unroll
            for (int mi = 0; mi < 4; ++mi) {
                const int base = (wm * 64 + mi * 16 + tr) * SROW + k0 + tc2;
                ah[mi][0] = *(const uint32_t*)(Ah + base);
                ah[mi][1] = *(const uint32_t*)(Ah + base + 8 * SROW);
                ah[mi][2] = *(const uint32_t*)(Ah + base + 8);
                ah[mi][3] = *(const uint32_t*)(Ah + base + 8 * SROW + 8);
            }
#pragma unroll
            for (int ni = 0; ni < 4; ++ni) {
                const int base = (wn * 32 + ni * 8 + tr) * SROW + k0 + tc2;
                bh[ni][0] = *(const uint32_t*)(Bh + base);
                bh[ni][1] = *(const uint32_t*)(Bh + base + 8);
            }
#pragma unroll
            for (int mi = 0; mi < 4; ++mi)
#pragma unroll
                for (int ni = 0; ni < 4; ++ni)
                    mma_f16(acc[mi][ni], ah[mi][0], ah[mi][1], ah[mi][2], ah[mi][3],
                            bh[ni][0], bh[ni][1]);
        }
        __syncthreads();
    }

#pragma unroll
    for (int mi = 0; mi < 4; ++mi) {
        const int r = bm + wm * 64 + mi * 16 + tr;
#pragma unroll
        for (int ni = 0; ni < 4; ++ni) {
            const int cidx = bn + wn * 32 + ni * 8 + tc2;
            const float b0 = bias[cidx], b1 = bias[cidx + 1];
            float2 v0 = make_float2(acc[mi][ni][0] + b0, acc[mi][ni][1] + b1);
            float2 v1 = make_float2(acc[mi][ni][2] + b0, acc[mi][ni][3] + b1);
            *(float2*)(C + (size_t)r * N + cidx)       = v0;
            *(float2*)(C + (size_t)(r + 8) * N + cidx) = v1;
        }
    }
}

// ---------------------------------------------------------------------------
extern "C" void kernel_launch(void* const* d_in, const int* in_sizes, int n_in,
                              void* d_out, int out_size)
{
    const float* x      = (const float*)d_in[0];
    const float* w_qkv  = (const float*)d_in[1];
    const float* b_qkv  = (const float*)d_in[2];
    const float* w_proj = (const float*)d_in[3];
    const float* b_proj = (const float*)d_in[4];
    float* out = (float*)d_out;

    __half *xf, *wq, *wph, *af, *q, *k, *vt;
    cudaGetSymbolAddress((void**)&xf, g_xf);
    cudaGetSymbolAddress((void**)&wq, g_wq);
    cudaGetSymbolAddress((void**)&wph, g_wph);
    cudaGetSymbolAddress((void**)&q, g_q);
    cudaGetSymbolAddress((void**)&k, g_k);
    cudaGetSymbolAddress((void**)&vt, g_vt);
    cudaGetSymbolAddress((void**)&af, g_af);

    cudaFuncSetAttribute(gemm_qkv,
                         cudaFuncAttributeMaxDynamicSharedMemorySize, GSMEM_SZ);
    cudaFuncSetAttribute(swa_tensor,
                         cudaFuncAttributeMaxDynamicSharedMemorySize, SWA_SMEM);
    cudaFuncSetAttribute(gemm_proj,
                         cudaFuncAttributeMaxDynamicSharedMemorySize, GSMEM_SZ);

    // fused input conversion (one launch)
    cvt_all<<<(N4X + N4Q + N4P) / 256, 256>>>(
        (const float4*)x, (const float4*)w_qkv, (const float4*)w_proj,
        xf, wq, wph);

    // 1) QKV projection (fp16 1-term) -> per-head fp16 Q,K + transposed V
    gemm_qkv<<<dim3(QKV_LD / BN, MTOT / BM), 256, GSMEM_SZ>>>(
        xf, wq, b_qkv, q, k, vt);

    // 2) sliding-window attention -> plain fp16
    swa_tensor<<<dim3(SEQ / 64, BHTOT), 128, SWA_SMEM>>>(q, k, vt, af);

    // 3) output projection (fp16 1-term)
    gemm_proj<<<dim3(D_MODEL / BN, MTOT / BM), 256, GSMEM_SZ>>>(
        af, wph, b_proj, out, MTOT, D_MODEL, D_MODEL);
}